// round 2
// baseline (speedup 1.0000x reference)
#include <cuda_runtime.h>

// ---------------------------------------------------------------------------
// Problem constants
// ---------------------------------------------------------------------------
// B=4, C_IN=256, C=128, H=W=64, HW=4096
// per-batch strides: res* = 128*4096 = 524288, difcat = 256*4096, logits = 1024*4096
// output: [4,128,128,128] float32
// ---------------------------------------------------------------------------

#define F_RES1 0
#define F_RES2 (F_RES1 + 2097152)
#define F_SIM  (F_RES2 + 2097152)
#define F_DIFC (F_SIM  + 16384)
#define F_ABSD (F_DIFC + 4194304)
#define F_SIMP (F_ABSD + 2097152)
#define F_R    (F_SIMP + 524288)
#define F_B0B1 (F_R    + 2097152)
#define F_DIF  (F_B0B1 + 2097152)
#define F_INC  (F_DIF  + 2097152)
#define F_LOG  (F_INC  + 2097152)
#define F_ACAT (F_LOG  + 16777216)
#define F_FUSE (F_ACAT + 4194304)
#define F_TOTAL (F_FUSE + 2097152)

__device__ float g_scratch[F_TOTAL];

// ---------------------------------------------------------------------------
// Generic fp32 GEMM: C[b,m,n] = sum_k A[(b),m,k or k,m] * B[b,k,n]  + epilogue
// Tiles 64x64x16, 256 threads, 4x4 per thread.
// aTrans==0: A row-major [M,K] (lda=K).  aTrans==1: A row-major [K,M] (lda=M).
// Epilogue: +bias[m]; if scale: relu then *scale[m]+off[m]; if resid: +resid.
// Requires M%64==0, N%64==0, K%16==0.
// ---------------------------------------------------------------------------
__global__ void gemm_k(const float* __restrict__ A, const float* __restrict__ B,
                       float* __restrict__ Cc,
                       const float* __restrict__ bias,
                       const float* __restrict__ scale, const float* __restrict__ off,
                       const float* __restrict__ resid,
                       int M, int N, int K,
                       long long Abatch, long long Bbatch, long long Cbatch, long long Rbatch,
                       int aTrans)
{
    __shared__ float As[16][65];
    __shared__ float Bs[16][64];
    const int b  = blockIdx.z;
    const int m0 = blockIdx.y * 64;
    const int n0 = blockIdx.x * 64;
    const float* Ab = A + (long long)b * Abatch;
    const float* Bb = B + (long long)b * Bbatch + n0;
    const int t  = threadIdx.x;
    const int tx = t & 15;   // n group
    const int ty = t >> 4;   // m group
    float acc[4][4];
#pragma unroll
    for (int i = 0; i < 4; i++)
#pragma unroll
        for (int j = 0; j < 4; j++) acc[i][j] = 0.f;

    for (int k0 = 0; k0 < K; k0 += 16) {
        if (aTrans == 0) {
            int ka = t & 15, ma = t >> 4;
#pragma unroll
            for (int r = 0; r < 4; r++)
                As[ka][ma + 16 * r] = Ab[(long long)(m0 + ma + 16 * r) * K + (k0 + ka)];
        } else {
            int ma = t & 63, ka = t >> 6;
#pragma unroll
            for (int r = 0; r < 4; r++)
                As[ka + 4 * r][ma] = Ab[(long long)(k0 + ka + 4 * r) * M + (m0 + ma)];
        }
        {
            int na = t & 63, ka = t >> 6;
#pragma unroll
            for (int r = 0; r < 4; r++)
                Bs[ka + 4 * r][na] = Bb[(long long)(k0 + ka + 4 * r) * N + na];
        }
        __syncthreads();
#pragma unroll
        for (int k = 0; k < 16; k++) {
            float a[4], bb[4];
#pragma unroll
            for (int i = 0; i < 4; i++) a[i] = As[k][ty * 4 + i];
#pragma unroll
            for (int j = 0; j < 4; j++) bb[j] = Bs[k][tx + 16 * j];
#pragma unroll
            for (int i = 0; i < 4; i++)
#pragma unroll
                for (int j = 0; j < 4; j++) acc[i][j] += a[i] * bb[j];
        }
        __syncthreads();
    }

#pragma unroll
    for (int i = 0; i < 4; i++) {
        int m = m0 + ty * 4 + i;
        float bi = bias  ? bias[m]  : 0.f;
        float sc = scale ? scale[m] : 1.f;
        float of = off   ? off[m]   : 0.f;
#pragma unroll
        for (int j = 0; j < 4; j++) {
            int n = n0 + tx + 16 * j;
            float v = acc[i][j] + bi;
            if (scale) v = fmaxf(v, 0.f) * sc + of;
            if (resid) v += resid[(long long)b * Rbatch + (long long)m * N + n];
            Cc[(long long)b * Cbatch + (long long)m * N + n] = v;
        }
    }
}

// ---------------------------------------------------------------------------
// Direct conv KSxKS (pad=KS/2), input [B,Cin,64,64], weights OIHW.
// Block: 256 threads, 32x32 spatial tile, 4 output channels, 4 pixels/thread.
// grid = (2, 2, B * Cout/4)
// ---------------------------------------------------------------------------
template <int KS>
__global__ void conv_k(const float* __restrict__ in, const float* __restrict__ w,
                       const float* __restrict__ bias,
                       const float* __restrict__ scale, const float* __restrict__ off,
                       float* __restrict__ out, long long out_bstride,
                       int Cin, int Cout)
{
    const int PAD = KS / 2;
    const int PS  = 32 + KS - 1;
    __shared__ float patch[PS * PS];
    __shared__ float wsm[4 * KS * KS];
    const int t  = threadIdx.x;
    const int tx = t & 31;      // col within tile
    const int ty = t >> 5;      // row group (0..7), handles rows ty+8r
    const int w0 = blockIdx.x * 32;
    const int h0 = blockIdx.y * 32;
    const int cog = blockIdx.z % (Cout / 4);
    const int b   = blockIdx.z / (Cout / 4);
    const int co0 = cog * 4;
    const float* inb = in + (long long)b * Cin * 4096;

    float acc[4][4];
#pragma unroll
    for (int c = 0; c < 4; c++)
#pragma unroll
        for (int r = 0; r < 4; r++) acc[c][r] = 0.f;

    for (int ci = 0; ci < Cin; ci++) {
        const float* ip = inb + ci * 4096;
        for (int idx = t; idx < PS * PS; idx += 256) {
            int py = idx / PS, px = idx % PS;
            int gh = h0 + py - PAD, gw = w0 + px - PAD;
            float v = 0.f;
            if (gh >= 0 && gh < 64 && gw >= 0 && gw < 64) v = ip[gh * 64 + gw];
            patch[idx] = v;
        }
        if (t < 4 * KS * KS) {
            int c4 = t / (KS * KS), kk = t % (KS * KS);
            wsm[t] = w[((long long)(co0 + c4) * Cin + ci) * (KS * KS) + kk];
        }
        __syncthreads();
#pragma unroll
        for (int kh = 0; kh < KS; kh++)
#pragma unroll
            for (int kw = 0; kw < KS; kw++) {
                float v[4];
#pragma unroll
                for (int r = 0; r < 4; r++)
                    v[r] = patch[(ty + 8 * r + kh) * PS + (tx + kw)];
#pragma unroll
                for (int c = 0; c < 4; c++) {
                    float wv = wsm[c * KS * KS + kh * KS + kw];
#pragma unroll
                    for (int r = 0; r < 4; r++) acc[c][r] += wv * v[r];
                }
            }
        __syncthreads();
    }

#pragma unroll
    for (int c = 0; c < 4; c++) {
        int co = co0 + c;
        float bi = bias[co];
        float sc = scale ? scale[co] : 1.f;
        float of = off   ? off[co]   : 0.f;
        float* ob = out + (long long)b * out_bstride + (long long)co * 4096;
#pragma unroll
        for (int r = 0; r < 4; r++) {
            float v = acc[c][r] + bi;
            if (scale) v = fmaxf(v, 0.f) * sc + of;
            ob[(h0 + ty + 8 * r) * 64 + (w0 + tx)] = v;
        }
    }
}

// ---------------------------------------------------------------------------
// Cosine similarity over contiguous 128-float chunks (row-major reshape!).
// One warp per (b,n) chunk; sim[b*4096+n].
// ---------------------------------------------------------------------------
__global__ void cos_k(const float* __restrict__ r1, const float* __restrict__ r2,
                      float* __restrict__ sim)
{
    int gid  = blockIdx.x * blockDim.x + threadIdx.x;
    int wid  = gid >> 5;
    int lane = gid & 31;
    if (wid >= 4 * 4096) return;
    const float* a = r1 + (long long)wid * 128;
    const float* c = r2 + (long long)wid * 128;
    float dot = 0.f, na = 0.f, nb = 0.f;
#pragma unroll
    for (int i = 0; i < 4; i++) {
        float x = a[lane + 32 * i], y = c[lane + 32 * i];
        dot += x * y; na += x * x; nb += y * y;
    }
#pragma unroll
    for (int o = 16; o; o >>= 1) {
        dot += __shfl_xor_sync(0xffffffffu, dot, o);
        na  += __shfl_xor_sync(0xffffffffu, na,  o);
        nb  += __shfl_xor_sync(0xffffffffu, nb,  o);
    }
    if (lane == 0)
        sim[wid] = dot / fmaxf(sqrtf(na) * sqrtf(nb), 1e-8f);
}

// ---------------------------------------------------------------------------
// dif1/dif2 (into difcat [B,256,4096]) and |sim1-sim2| (absd [B,128,4096]).
// f[b,n,c] = res_flat[b][n*128+c]; res[b,c,n] = res_flat[b][c*4096+n].
// Per-batch stride of res1/res2/absd = 128*4096 = 524288 floats.  (FIXED)
// Tile 32c x 32n with SMEM transpose for the f-orientation.
// grid = (4096/32, 128/32, 4), 256 threads.
// ---------------------------------------------------------------------------
__global__ void difsim_k(const float* __restrict__ r1, const float* __restrict__ r2,
                         const float* __restrict__ sim,
                         float* __restrict__ difcat, float* __restrict__ absd)
{
    __shared__ float f1s[32][33], f2s[32][33], ss[32];
    const int b  = blockIdx.z;
    const int c0 = blockIdx.y * 32;
    const int n0 = blockIdx.x * 32;
    const int t  = threadIdx.x;
    const int tx = t & 31, ty = t >> 5;
    const long long BS = 524288;  // per-batch stride of res buffers
    const float* r1b = r1 + (long long)b * BS;
    const float* r2b = r2 + (long long)b * BS;
#pragma unroll
    for (int r = 0; r < 4; r++) {
        int n = ty + 8 * r;
        f1s[n][tx] = r1b[(long long)(n0 + n) * 128 + c0 + tx];
        f2s[n][tx] = r2b[(long long)(n0 + n) * 128 + c0 + tx];
    }
    if (t < 32) ss[t] = sim[b * 4096 + n0 + t];
    __syncthreads();
#pragma unroll
    for (int r = 0; r < 4; r++) {
        int c = c0 + ty + 8 * r;
        int n = n0 + tx;
        float rv1 = r1b[(long long)c * 4096 + n];
        float rv2 = r2b[(long long)c * 4096 + n];
        float s  = ss[tx];
        float f1 = f1s[tx][ty + 8 * r];
        float f2 = f2s[tx][ty + 8 * r];
        float omns = 1.f - s;
        long long bo = (long long)b * (256LL * 4096) + (long long)c * 4096 + n;
        difcat[bo]                 = f1 * omns + rv1;
        difcat[bo + 128LL * 4096]  = f2 * omns + rv2;
        absd[(long long)b * BS + (long long)c * 4096 + n] =
            fabsf((f1 - f2) * s + rv1 - rv2);
    }
}

// AvgPool2d(2,2): absd [B,128,64,64] -> simp [B,128,32,32]
__global__ void pool_k(const float* __restrict__ absd, float* __restrict__ simp)
{
    int i = blockIdx.x * 256 + threadIdx.x;
    if (i >= 524288) return;
    int wp = i & 31, hp = (i >> 5) & 31, bc = i >> 10;
    const float* a = absd + (long long)bc * 4096 + (hp * 2) * 64 + wp * 2;
    simp[i] = 0.25f * (a[0] + a[1] + a[64] + a[65]);
}

// Row softmax over 4096, in place; one block per row (4096 rows total).
__global__ void softmax_k(float* __restrict__ logits)
{
    __shared__ float red[256];
    float* p = logits + (long long)blockIdx.x * 4096;
    const int t = threadIdx.x;
    float v[16];
    float mx = -1e30f;
#pragma unroll
    for (int i = 0; i < 16; i++) { v[i] = p[t + 256 * i]; mx = fmaxf(mx, v[i]); }
    red[t] = mx; __syncthreads();
    for (int o = 128; o; o >>= 1) {
        if (t < o) red[t] = fmaxf(red[t], red[t + o]);
        __syncthreads();
    }
    mx = red[0]; __syncthreads();
    float sum = 0.f;
#pragma unroll
    for (int i = 0; i < 16; i++) { v[i] = __expf(v[i] - mx); sum += v[i]; }
    red[t] = sum; __syncthreads();
    for (int o = 128; o; o >>= 1) {
        if (t < o) red[t] += red[t + o];
        __syncthreads();
    }
    float inv = 1.f / red[0];
#pragma unroll
    for (int i = 0; i < 16; i++) p[t + 256 * i] = v[i] * inv;
}

// Bilinear x2 upsample (half-pixel, edge clamp): [B,128,64,64] -> [B,128,128,128]
__global__ void resize_k(const float* __restrict__ in, float* __restrict__ out)
{
    long long i = (long long)blockIdx.x * 256 + threadIdx.x;
    if (i >= 8388608LL) return;
    int x = (int)(i & 127), y = (int)((i >> 7) & 127);
    long long bc = i >> 14;
    float sx = (x + 0.5f) * 0.5f - 0.5f;
    float sy = (y + 0.5f) * 0.5f - 0.5f;
    int x0 = (int)floorf(sx), y0 = (int)floorf(sy);
    float fx = sx - x0, fy = sy - y0;
    int x1 = min(x0 + 1, 63), y1 = min(y0 + 1, 63);
    x0 = max(x0, 0); y0 = max(y0, 0);
    const float* p = in + bc * 4096;
    float v = (1.f - fy) * ((1.f - fx) * p[y0 * 64 + x0] + fx * p[y0 * 64 + x1])
            +        fy  * ((1.f - fx) * p[y1 * 64 + x0] + fx * p[y1 * 64 + x1]);
    out[i] = v;
}

// ---------------------------------------------------------------------------
extern "C" void kernel_launch(void* const* d_in, const int* in_sizes, int n_in,
                              void* d_out, int out_size)
{
    (void)in_sizes; (void)n_in; (void)out_size;
    const float* t1      = (const float*)d_in[0];
    const float* t2      = (const float*)d_in[1];
    const float* t1_w    = (const float*)d_in[2];
    const float* t1_b    = (const float*)d_in[3];
    const float* t2_w    = (const float*)d_in[4];
    const float* t2_b    = (const float*)d_in[5];
    const float* df_res_w = (const float*)d_in[6];
    const float* df_res_b = (const float*)d_in[7];
    const float* df_res_s = (const float*)d_in[8];
    const float* df_res_o = (const float*)d_in[9];
    const float* df_b0_w = (const float*)d_in[10];
    const float* df_b0_b = (const float*)d_in[11];
    const float* df_b0_s = (const float*)d_in[12];
    const float* df_b0_o = (const float*)d_in[13];
    const float* df_b1_w = (const float*)d_in[14];
    const float* df_b1_b = (const float*)d_in[15];
    const float* df_b1_s = (const float*)d_in[16];
    const float* df_b1_o = (const float*)d_in[17];
    const float* df_fu_w = (const float*)d_in[18];
    const float* df_fu_b = (const float*)d_in[19];
    const float* df_fu_s = (const float*)d_in[20];
    const float* df_fu_o = (const float*)d_in[21];
    const float* br1_w   = (const float*)d_in[22];
    const float* br1_b   = (const float*)d_in[23];
    const float* br2_w   = (const float*)d_in[24];
    const float* br2_b   = (const float*)d_in[25];
    const float* fu_w    = (const float*)d_in[26];
    const float* fu_b    = (const float*)d_in[27];
    const float* fu_s    = (const float*)d_in[28];
    const float* fu_o    = (const float*)d_in[29];
    float* out = (float*)d_out;

    float* S;
    cudaGetSymbolAddress((void**)&S, g_scratch);
    float* res1   = S + F_RES1;
    float* res2   = S + F_RES2;
    float* sim    = S + F_SIM;
    float* difcat = S + F_DIFC;
    float* absd   = S + F_ABSD;
    float* simp   = S + F_SIMP;
    float* rbuf   = S + F_R;
    float* b0b1   = S + F_B0B1;
    float* dif    = S + F_DIF;
    float* inc    = S + F_INC;
    float* logits = S + F_LOG;
    float* acat   = S + F_ACAT;
    float* fuse   = S + F_FUSE;

    const long long S128 = 128LL * 4096;
    const long long S256 = 256LL * 4096;
    const long long SLOG = 1024LL * 4096;

    // 1. res1/res2 = 1x1 conv (256->128) + bias
    gemm_k<<<dim3(64, 2, 4), 256>>>(t1_w, t1, res1, t1_b, nullptr, nullptr, nullptr,
                                    128, 4096, 256, 0, S256, S128, 0, 0);
    gemm_k<<<dim3(64, 2, 4), 256>>>(t2_w, t2, res2, t2_b, nullptr, nullptr, nullptr,
                                    128, 4096, 256, 0, S256, S128, 0, 0);
    // 2. cosine similarity over contiguous 128-chunks
    cos_k<<<2048, 256>>>(res1, res2, sim);
    // 3. dif1/dif2 + |sim1-sim2|
    difsim_k<<<dim3(128, 4, 4), 256>>>(res1, res2, sim, difcat, absd);
    // 4. avgpool -> simp (== attn)
    pool_k<<<2048, 256>>>(absd, simp);
    // 5. r = stdconv 1x1 (256->128)
    gemm_k<<<dim3(64, 2, 4), 256>>>(df_res_w, difcat, rbuf, df_res_b, df_res_s, df_res_o,
                                    nullptr, 128, 4096, 256, 0, S256, S128, 0, 0);
    // 6/7. b0 (3x3, 128->64) and b1 (5x5, 128->64) into cat buffer
    conv_k<3><<<dim3(2, 2, 4 * 16), 256>>>(rbuf, df_b0_w, df_b0_b, df_b0_s, df_b0_o,
                                           b0b1, S128, 128, 64);
    conv_k<5><<<dim3(2, 2, 4 * 16), 256>>>(rbuf, df_b1_w, df_b1_b, df_b1_s, df_b1_o,
                                           b0b1 + 64LL * 4096, S128, 128, 64);
    // 8. dif = stdconv 1x1 (128->128) + r
    gemm_k<<<dim3(64, 2, 4), 256>>>(df_fu_w, b0b1, dif, df_fu_b, df_fu_s, df_fu_o,
                                    rbuf, 128, 4096, 128, 0, S128, S128, S128, 0);
    // --- branch 1: inc1 = conv3x3(dif) + bias; attention; a1 -> acat[:, :128] ---
    conv_k<3><<<dim3(2, 2, 4 * 32), 256>>>(dif, br1_w, br1_b, nullptr, nullptr,
                                           inc, S128, 128, 128);
    gemm_k<<<dim3(64, 16, 4), 256>>>(simp, inc, logits, nullptr, nullptr, nullptr, nullptr,
                                     1024, 4096, 128, 131072, S128, SLOG, 0, 0);
    softmax_k<<<4096, 256>>>(logits);
    gemm_k<<<dim3(64, 2, 4), 256>>>(simp, logits, acat, nullptr, nullptr, nullptr,
                                    inc, 128, 4096, 1024, 131072, SLOG, S256, S128, 1);
    // --- branch 2: inc2 = conv5x5(dif); attention; a2 -> acat[:, 128:] ---
    conv_k<5><<<dim3(2, 2, 4 * 32), 256>>>(dif, br2_w, br2_b, nullptr, nullptr,
                                           inc, S128, 128, 128);
    gemm_k<<<dim3(64, 16, 4), 256>>>(simp, inc, logits, nullptr, nullptr, nullptr, nullptr,
                                     1024, 4096, 128, 131072, S128, SLOG, 0, 0);
    softmax_k<<<4096, 256>>>(logits);
    gemm_k<<<dim3(64, 2, 4), 256>>>(simp, logits, acat + 128LL * 4096, nullptr, nullptr, nullptr,
                                    inc, 128, 4096, 1024, 131072, SLOG, S256, S128, 1);
    // 14. fused = stdconv 1x1 (256->128) + dif
    gemm_k<<<dim3(64, 2, 4), 256>>>(fu_w, acat, fuse, fu_b, fu_s, fu_o,
                                    dif, 128, 4096, 256, 0, S256, S128, S128, 0);
    // 15. bilinear x2 upsample to output
    resize_k<<<32768, 256>>>(fuse, out);
}

// round 3
// speedup vs baseline: 1.2650x; 1.2650x over previous
#include <cuda_runtime.h>

// ---------------------------------------------------------------------------
// B=4, C_IN=256, C=128, H=W=64, HW=4096
// output: [4,128,128,128] float32
// ---------------------------------------------------------------------------

#define F_RES1 0
#define F_RES2 (F_RES1 + 2097152)
#define F_SIM  (F_RES2 + 2097152)
#define F_DIFC (F_SIM  + 16384)
#define F_ABSD (F_DIFC + 4194304)
#define F_SIMP (F_ABSD + 2097152)
#define F_R    (F_SIMP + 524288)
#define F_B0B1 (F_R    + 2097152)
#define F_DIF  (F_B0B1 + 2097152)
#define F_INC  (F_DIF  + 2097152)
#define F_LOG  (F_INC  + 2097152)
#define F_ACAT (F_LOG  + 16777216)
#define F_FUSE (F_ACAT + 4194304)
#define F_TOTAL (F_FUSE + 2097152)

__device__ float g_scratch[F_TOTAL];

// ---------------------------------------------------------------------------
// High-throughput fp32 GEMM: tile 128x128, k-step 16, 256 threads, 8x8 micro.
// Double-buffered SMEM, float4 global loads, LDS.128 smem reads.
// aTrans==0: A row-major [M,K]. aTrans==1: A row-major [K,M] (M==multiple of 128).
// C[b,m,n] = sum_k A.B + bias[m]; if scale: relu->*scale[m]+off[m]; +resid.
// Requires M%128==0, N%128==0, K%16==0.
// ---------------------------------------------------------------------------
__global__ void __launch_bounds__(256, 2) gemm128_k(
    const float* __restrict__ A, const float* __restrict__ B, float* __restrict__ Cc,
    const float* __restrict__ bias, const float* __restrict__ scale,
    const float* __restrict__ off, const float* __restrict__ resid,
    int M, int N, int K,
    long long Abatch, long long Bbatch, long long Cbatch, long long Rbatch,
    int aTrans)
{
    __shared__ __align__(16) float As[2][16][128];
    __shared__ __align__(16) float Bs[2][16][128];
    const int b  = blockIdx.z;
    const int m0 = blockIdx.y * 128;
    const int n0 = blockIdx.x * 128;
    const float* Ab = A + (long long)b * Abatch;
    const float* Bb = B + (long long)b * Bbatch + n0;
    const int t  = threadIdx.x;
    const int tx = t & 15;
    const int ty = t >> 4;

    float acc[8][8];
#pragma unroll
    for (int i = 0; i < 8; i++)
#pragma unroll
        for (int j = 0; j < 8; j++) acc[i][j] = 0.f;

    float4 ra[2], rb[2];

    auto pref = [&](int k0) {
        if (aTrans == 0) {
#pragma unroll
            for (int r = 0; r < 2; r++) {
                int f = t + 256 * r, row = f >> 2, kq = f & 3;
                ra[r] = *(const float4*)&Ab[(long long)(m0 + row) * K + k0 + kq * 4];
            }
        } else {
#pragma unroll
            for (int r = 0; r < 2; r++) {
                int f = t + 256 * r, k = f >> 5, mq = f & 31;
                ra[r] = *(const float4*)&Ab[(long long)(k0 + k) * M + m0 + mq * 4];
            }
        }
#pragma unroll
        for (int r = 0; r < 2; r++) {
            int f = t + 256 * r, k = f >> 5, nq = f & 31;
            rb[r] = *(const float4*)&Bb[(long long)(k0 + k) * N + nq * 4];
        }
    };
    auto stob = [&](int buf) {
        if (aTrans == 0) {
#pragma unroll
            for (int r = 0; r < 2; r++) {
                int f = t + 256 * r, row = f >> 2, kq = f & 3;
                As[buf][kq * 4 + 0][row] = ra[r].x;
                As[buf][kq * 4 + 1][row] = ra[r].y;
                As[buf][kq * 4 + 2][row] = ra[r].z;
                As[buf][kq * 4 + 3][row] = ra[r].w;
            }
        } else {
#pragma unroll
            for (int r = 0; r < 2; r++) {
                int f = t + 256 * r, k = f >> 5, mq = f & 31;
                *(float4*)&As[buf][k][mq * 4] = ra[r];
            }
        }
#pragma unroll
        for (int r = 0; r < 2; r++) {
            int f = t + 256 * r, k = f >> 5, nq = f & 31;
            *(float4*)&Bs[buf][k][nq * 4] = rb[r];
        }
    };

    pref(0); stob(0); __syncthreads();
    int buf = 0;
    for (int k0 = 0; k0 < K; k0 += 16) {
        bool more = (k0 + 16) < K;
        if (more) pref(k0 + 16);
#pragma unroll
        for (int kk = 0; kk < 16; kk++) {
            float4 a0 = *(const float4*)&As[buf][kk][ty * 8];
            float4 a1 = *(const float4*)&As[buf][kk][ty * 8 + 4];
            float4 b0 = *(const float4*)&Bs[buf][kk][tx * 8];
            float4 b1 = *(const float4*)&Bs[buf][kk][tx * 8 + 4];
            float aa[8] = {a0.x, a0.y, a0.z, a0.w, a1.x, a1.y, a1.z, a1.w};
            float bb[8] = {b0.x, b0.y, b0.z, b0.w, b1.x, b1.y, b1.z, b1.w};
#pragma unroll
            for (int i = 0; i < 8; i++)
#pragma unroll
                for (int j = 0; j < 8; j++) acc[i][j] += aa[i] * bb[j];
        }
        if (more) { stob(buf ^ 1); __syncthreads(); buf ^= 1; }
    }

#pragma unroll
    for (int i = 0; i < 8; i++) {
        int m = m0 + ty * 8 + i;
        float bi = bias  ? bias[m]  : 0.f;
        float sc = scale ? scale[m] : 1.f;
        float of = off   ? off[m]   : 0.f;
        float* cp = Cc + (long long)b * Cbatch + (long long)m * N + n0 + tx * 8;
        const float* rp = resid ? (resid + (long long)b * Rbatch + (long long)m * N + n0 + tx * 8)
                                : nullptr;
        float v[8];
#pragma unroll
        for (int j = 0; j < 8; j++) {
            v[j] = acc[i][j] + bi;
            if (scale) v[j] = fmaxf(v[j], 0.f) * sc + of;
        }
        if (rp) {
            float4 r0 = *(const float4*)rp, r1 = *(const float4*)(rp + 4);
            v[0] += r0.x; v[1] += r0.y; v[2] += r0.z; v[3] += r0.w;
            v[4] += r1.x; v[5] += r1.y; v[6] += r1.z; v[7] += r1.w;
        }
        *(float4*)cp       = make_float4(v[0], v[1], v[2], v[3]);
        *(float4*)(cp + 4) = make_float4(v[4], v[5], v[6], v[7]);
    }
}

// ---------------------------------------------------------------------------
// Implicit-GEMM conv KSxKS (pad=KS/2) on [B,Cin,64,64], weights OIHW
// (naturally [Cout, Cin*KS*KS] row-major). Tile MT x 128 pixels, k-step 16.
// MT=128 -> 8x8 micro; MT=64 -> 4x8 micro. grid = (32, 1, B).
// ---------------------------------------------------------------------------
template <int KS, int MT>
__global__ void __launch_bounds__(256, 2) convig_k(
    const float* __restrict__ in, const float* __restrict__ w,
    const float* __restrict__ bias, const float* __restrict__ scale,
    const float* __restrict__ off,
    float* __restrict__ out, long long out_bstride, int Cin)
{
    constexpr int KS2 = KS * KS;
    constexpr int P   = KS / 2;
    constexpr int MR  = MT / 16;    // rows per thread
    constexpr int ALD = MT / 64;    // float4 A loads per thread
    __shared__ __align__(16) float As[2][16][MT];
    __shared__ __align__(16) float Bs[2][16][128];
    const int t  = threadIdx.x;
    const int tx = t & 15;
    const int ty = t >> 4;
    const int n0 = blockIdx.x * 128;
    const int b  = blockIdx.z;
    const float* inb = in + (long long)b * Cin * 4096;
    const int K = Cin * KS2;
    // B-load mapping: one k-row, 8 consecutive pixels per thread
    const int krow  = t >> 4;
    const int ng    = t & 15;
    const int nb    = n0 + ng * 8;
    const int ybase = nb >> 6;
    const int xbase = nb & 63;

    float acc[MR][8];
#pragma unroll
    for (int i = 0; i < MR; i++)
#pragma unroll
        for (int j = 0; j < 8; j++) acc[i][j] = 0.f;

    float rbv[8];
    float4 ra[ALD];

    auto pref = [&](int k0) {
        int k  = k0 + krow;
        int ci = k / KS2;
        int tap = k - ci * KS2;
        int dy = tap / KS - P, dx = tap % KS - P;
        int y  = ybase + dy;
        const float* ip = inb + (long long)ci * 4096 + y * 64;
        bool yok = ((unsigned)y < 64u);
#pragma unroll
        for (int j = 0; j < 8; j++) {
            int xx = xbase + j + dx;
            rbv[j] = (yok && (unsigned)xx < 64u) ? ip[xx] : 0.f;
        }
#pragma unroll
        for (int r = 0; r < ALD; r++) {
            int f = t + 256 * r, row = f >> 2, kq = f & 3;
            ra[r] = *(const float4*)&w[(long long)row * K + k0 + kq * 4];
        }
    };
    auto stob = [&](int buf) {
#pragma unroll
        for (int j = 0; j < 8; j++) Bs[buf][krow][ng * 8 + j] = rbv[j];
#pragma unroll
        for (int r = 0; r < ALD; r++) {
            int f = t + 256 * r, row = f >> 2, kq = f & 3;
            As[buf][kq * 4 + 0][row] = ra[r].x;
            As[buf][kq * 4 + 1][row] = ra[r].y;
            As[buf][kq * 4 + 2][row] = ra[r].z;
            As[buf][kq * 4 + 3][row] = ra[r].w;
        }
    };

    pref(0); stob(0); __syncthreads();
    int buf = 0;
    for (int k0 = 0; k0 < K; k0 += 16) {
        bool more = (k0 + 16) < K;
        if (more) pref(k0 + 16);
#pragma unroll
        for (int kk = 0; kk < 16; kk++) {
            float4 b0 = *(const float4*)&Bs[buf][kk][tx * 8];
            float4 b1 = *(const float4*)&Bs[buf][kk][tx * 8 + 4];
            float bb[8] = {b0.x, b0.y, b0.z, b0.w, b1.x, b1.y, b1.z, b1.w};
            float aa[MR];
            if (MR == 8) {
                float4 a0 = *(const float4*)&As[buf][kk][ty * 8];
                float4 a1 = *(const float4*)&As[buf][kk][ty * 8 + 4];
                aa[0] = a0.x; aa[1] = a0.y; aa[2] = a0.z; aa[3] = a0.w;
                aa[4] = a1.x; aa[5] = a1.y; aa[6] = a1.z; aa[7] = a1.w;
            } else {
                float4 a0 = *(const float4*)&As[buf][kk][ty * 4];
                aa[0] = a0.x; aa[1] = a0.y; aa[2] = a0.z; aa[3] = a0.w;
            }
#pragma unroll
            for (int i = 0; i < MR; i++)
#pragma unroll
                for (int j = 0; j < 8; j++) acc[i][j] += aa[i] * bb[j];
        }
        if (more) { stob(buf ^ 1); __syncthreads(); buf ^= 1; }
    }

#pragma unroll
    for (int i = 0; i < MR; i++) {
        int co = ty * MR + i;
        float bi = bias[co];
        float sc = scale ? scale[co] : 1.f;
        float of = off   ? off[co]   : 0.f;
        float* op = out + (long long)b * out_bstride + (long long)co * 4096 + n0 + tx * 8;
        float v[8];
#pragma unroll
        for (int j = 0; j < 8; j++) {
            v[j] = acc[i][j] + bi;
            if (scale) v[j] = fmaxf(v[j], 0.f) * sc + of;
        }
        *(float4*)op       = make_float4(v[0], v[1], v[2], v[3]);
        *(float4*)(op + 4) = make_float4(v[4], v[5], v[6], v[7]);
    }
}

// ---------------------------------------------------------------------------
// Cosine similarity over contiguous 128-float chunks. One warp per chunk.
// ---------------------------------------------------------------------------
__global__ void cos_k(const float* __restrict__ r1, const float* __restrict__ r2,
                      float* __restrict__ sim)
{
    int gid  = blockIdx.x * blockDim.x + threadIdx.x;
    int wid  = gid >> 5;
    int lane = gid & 31;
    if (wid >= 4 * 4096) return;
    const float* a = r1 + (long long)wid * 128;
    const float* c = r2 + (long long)wid * 128;
    float dot = 0.f, na = 0.f, nb = 0.f;
#pragma unroll
    for (int i = 0; i < 4; i++) {
        float x = a[lane + 32 * i], y = c[lane + 32 * i];
        dot += x * y; na += x * x; nb += y * y;
    }
#pragma unroll
    for (int o = 16; o; o >>= 1) {
        dot += __shfl_xor_sync(0xffffffffu, dot, o);
        na  += __shfl_xor_sync(0xffffffffu, na,  o);
        nb  += __shfl_xor_sync(0xffffffffu, nb,  o);
    }
    if (lane == 0)
        sim[wid] = dot / fmaxf(sqrtf(na) * sqrtf(nb), 1e-8f);
}

// ---------------------------------------------------------------------------
// dif1/dif2 (difcat [B,256,4096]) and |sim1-sim2| (absd [B,128,4096]).
// ---------------------------------------------------------------------------
__global__ void difsim_k(const float* __restrict__ r1, const float* __restrict__ r2,
                         const float* __restrict__ sim,
                         float* __restrict__ difcat, float* __restrict__ absd)
{
    __shared__ float f1s[32][33], f2s[32][33], ss[32];
    const int b  = blockIdx.z;
    const int c0 = blockIdx.y * 32;
    const int n0 = blockIdx.x * 32;
    const int t  = threadIdx.x;
    const int tx = t & 31, ty = t >> 5;
    const long long BS = 524288;
    const float* r1b = r1 + (long long)b * BS;
    const float* r2b = r2 + (long long)b * BS;
#pragma unroll
    for (int r = 0; r < 4; r++) {
        int n = ty + 8 * r;
        f1s[n][tx] = r1b[(long long)(n0 + n) * 128 + c0 + tx];
        f2s[n][tx] = r2b[(long long)(n0 + n) * 128 + c0 + tx];
    }
    if (t < 32) ss[t] = sim[b * 4096 + n0 + t];
    __syncthreads();
#pragma unroll
    for (int r = 0; r < 4; r++) {
        int c = c0 + ty + 8 * r;
        int n = n0 + tx;
        float rv1 = r1b[(long long)c * 4096 + n];
        float rv2 = r2b[(long long)c * 4096 + n];
        float s  = ss[tx];
        float f1 = f1s[tx][ty + 8 * r];
        float f2 = f2s[tx][ty + 8 * r];
        float omns = 1.f - s;
        long long bo = (long long)b * (256LL * 4096) + (long long)c * 4096 + n;
        difcat[bo]                = f1 * omns + rv1;
        difcat[bo + 128LL * 4096] = f2 * omns + rv2;
        absd[(long long)b * BS + (long long)c * 4096 + n] =
            fabsf((f1 - f2) * s + rv1 - rv2);
    }
}

// AvgPool2d(2,2): absd [B,128,64,64] -> simp [B,128,32,32]
__global__ void pool_k(const float* __restrict__ absd, float* __restrict__ simp)
{
    int i = blockIdx.x * 256 + threadIdx.x;
    if (i >= 524288) return;
    int wp = i & 31, hp = (i >> 5) & 31, bc = i >> 10;
    const float* a = absd + (long long)bc * 4096 + (hp * 2) * 64 + wp * 2;
    simp[i] = 0.25f * (a[0] + a[1] + a[64] + a[65]);
}

// Row softmax over 4096, in place; one block per row.
__global__ void softmax_k(float* __restrict__ logits)
{
    __shared__ float red[256];
    float* p = logits + (long long)blockIdx.x * 4096;
    const int t = threadIdx.x;
    float v[16];
    float mx = -1e30f;
#pragma unroll
    for (int i = 0; i < 16; i++) { v[i] = p[t + 256 * i]; mx = fmaxf(mx, v[i]); }
    red[t] = mx; __syncthreads();
    for (int o = 128; o; o >>= 1) {
        if (t < o) red[t] = fmaxf(red[t], red[t + o]);
        __syncthreads();
    }
    mx = red[0]; __syncthreads();
    float sum = 0.f;
#pragma unroll
    for (int i = 0; i < 16; i++) { v[i] = __expf(v[i] - mx); sum += v[i]; }
    red[t] = sum; __syncthreads();
    for (int o = 128; o; o >>= 1) {
        if (t < o) red[t] += red[t + o];
        __syncthreads();
    }
    float inv = 1.f / red[0];
#pragma unroll
    for (int i = 0; i < 16; i++) p[t + 256 * i] = v[i] * inv;
}

// Bilinear x2 upsample: [B,128,64,64] -> [B,128,128,128]
__global__ void resize_k(const float* __restrict__ in, float* __restrict__ out)
{
    long long i = (long long)blockIdx.x * 256 + threadIdx.x;
    if (i >= 8388608LL) return;
    int x = (int)(i & 127), y = (int)((i >> 7) & 127);
    long long bc = i >> 14;
    float sx = (x + 0.5f) * 0.5f - 0.5f;
    float sy = (y + 0.5f) * 0.5f - 0.5f;
    int x0 = (int)floorf(sx), y0 = (int)floorf(sy);
    float fx = sx - x0, fy = sy - y0;
    int x1 = min(x0 + 1, 63), y1 = min(y0 + 1, 63);
    x0 = max(x0, 0); y0 = max(y0, 0);
    const float* p = in + bc * 4096;
    float v = (1.f - fy) * ((1.f - fx) * p[y0 * 64 + x0] + fx * p[y0 * 64 + x1])
            +        fy  * ((1.f - fx) * p[y1 * 64 + x0] + fx * p[y1 * 64 + x1]);
    out[i] = v;
}

// ---------------------------------------------------------------------------
extern "C" void kernel_launch(void* const* d_in, const int* in_sizes, int n_in,
                              void* d_out, int out_size)
{
    (void)in_sizes; (void)n_in; (void)out_size;
    const float* t1      = (const float*)d_in[0];
    const float* t2      = (const float*)d_in[1];
    const float* t1_w    = (const float*)d_in[2];
    const float* t1_b    = (const float*)d_in[3];
    const float* t2_w    = (const float*)d_in[4];
    const float* t2_b    = (const float*)d_in[5];
    const float* df_res_w = (const float*)d_in[6];
    const float* df_res_b = (const float*)d_in[7];
    const float* df_res_s = (const float*)d_in[8];
    const float* df_res_o = (const float*)d_in[9];
    const float* df_b0_w = (const float*)d_in[10];
    const float* df_b0_b = (const float*)d_in[11];
    const float* df_b0_s = (const float*)d_in[12];
    const float* df_b0_o = (const float*)d_in[13];
    const float* df_b1_w = (const float*)d_in[14];
    const float* df_b1_b = (const float*)d_in[15];
    const float* df_b1_s = (const float*)d_in[16];
    const float* df_b1_o = (const float*)d_in[17];
    const float* df_fu_w = (const float*)d_in[18];
    const float* df_fu_b = (const float*)d_in[19];
    const float* df_fu_s = (const float*)d_in[20];
    const float* df_fu_o = (const float*)d_in[21];
    const float* br1_w   = (const float*)d_in[22];
    const float* br1_b   = (const float*)d_in[23];
    const float* br2_w   = (const float*)d_in[24];
    const float* br2_b   = (const float*)d_in[25];
    const float* fu_w    = (const float*)d_in[26];
    const float* fu_b    = (const float*)d_in[27];
    const float* fu_s    = (const float*)d_in[28];
    const float* fu_o    = (const float*)d_in[29];
    float* out = (float*)d_out;

    float* S;
    cudaGetSymbolAddress((void**)&S, g_scratch);
    float* res1   = S + F_RES1;
    float* res2   = S + F_RES2;
    float* sim    = S + F_SIM;
    float* difcat = S + F_DIFC;
    float* absd   = S + F_ABSD;
    float* simp   = S + F_SIMP;
    float* rbuf   = S + F_R;
    float* b0b1   = S + F_B0B1;
    float* dif    = S + F_DIF;
    float* inc    = S + F_INC;
    float* logits = S + F_LOG;
    float* acat   = S + F_ACAT;
    float* fuse   = S + F_FUSE;

    const long long S128 = 128LL * 4096;
    const long long S256 = 256LL * 4096;
    const long long SLOG = 1024LL * 4096;

    // 1. res1/res2 = 1x1 conv (256->128) + bias
    gemm128_k<<<dim3(32, 1, 4), 256>>>(t1_w, t1, res1, t1_b, nullptr, nullptr, nullptr,
                                       128, 4096, 256, 0, S256, S128, 0, 0);
    gemm128_k<<<dim3(32, 1, 4), 256>>>(t2_w, t2, res2, t2_b, nullptr, nullptr, nullptr,
                                       128, 4096, 256, 0, S256, S128, 0, 0);
    // 2. cosine similarity
    cos_k<<<2048, 256>>>(res1, res2, sim);
    // 3. dif1/dif2 + |sim1-sim2|
    difsim_k<<<dim3(128, 4, 4), 256>>>(res1, res2, sim, difcat, absd);
    // 4. avgpool -> simp (== attn)
    pool_k<<<2048, 256>>>(absd, simp);
    // 5. r = stdconv 1x1 (256->128)
    gemm128_k<<<dim3(32, 1, 4), 256>>>(df_res_w, difcat, rbuf, df_res_b, df_res_s, df_res_o,
                                       nullptr, 128, 4096, 256, 0, S256, S128, 0, 0);
    // 6/7. b0 (3x3, 128->64) and b1 (5x5, 128->64) into cat buffer
    convig_k<3, 64><<<dim3(32, 1, 4), 256>>>(rbuf, df_b0_w, df_b0_b, df_b0_s, df_b0_o,
                                             b0b1, S128, 128);
    convig_k<5, 64><<<dim3(32, 1, 4), 256>>>(rbuf, df_b1_w, df_b1_b, df_b1_s, df_b1_o,
                                             b0b1 + 64LL * 4096, S128, 128);
    // 8. dif = stdconv 1x1 (128->128) + r
    gemm128_k<<<dim3(32, 1, 4), 256>>>(df_fu_w, b0b1, dif, df_fu_b, df_fu_s, df_fu_o,
                                       rbuf, 128, 4096, 128, 0, S128, S128, S128, 0);
    // --- branch 1: inc1 = conv3x3(dif)+bias; attention; a1 -> acat[:, :128] ---
    convig_k<3, 128><<<dim3(32, 1, 4), 256>>>(dif, br1_w, br1_b, nullptr, nullptr,
                                              inc, S128, 128);
    gemm128_k<<<dim3(32, 8, 4), 256>>>(simp, inc, logits, nullptr, nullptr, nullptr, nullptr,
                                       1024, 4096, 128, 131072, S128, SLOG, 0, 0);
    softmax_k<<<4096, 256>>>(logits);
    gemm128_k<<<dim3(32, 1, 4), 256>>>(simp, logits, acat, nullptr, nullptr, nullptr,
                                       inc, 128, 4096, 1024, 131072, SLOG, S256, S128, 1);
    // --- branch 2: inc2 = conv5x5(dif); attention; a2 -> acat[:, 128:] ---
    convig_k<5, 128><<<dim3(32, 1, 4), 256>>>(dif, br2_w, br2_b, nullptr, nullptr,
                                              inc, S128, 128);
    gemm128_k<<<dim3(32, 8, 4), 256>>>(simp, inc, logits, nullptr, nullptr, nullptr, nullptr,
                                       1024, 4096, 128, 131072, S128, SLOG, 0, 0);
    softmax_k<<<4096, 256>>>(logits);
    gemm128_k<<<dim3(32, 1, 4), 256>>>(simp, logits, acat + 128LL * 4096, nullptr, nullptr, nullptr,
                                       inc, 128, 4096, 1024, 131072, SLOG, S256, S128, 1);
    // 14. fused = stdconv 1x1 (256->128) + dif
    gemm128_k<<<dim3(32, 1, 4), 256>>>(fu_w, acat, fuse, fu_b, fu_s, fu_o,
                                       dif, 128, 4096, 256, 0, S256, S128, S128, 0);
    // 15. bilinear x2 upsample to output
    resize_k<<<32768, 256>>>(fuse, out);
}

// round 4
// speedup vs baseline: 1.2658x; 1.0007x over previous
#include <cuda_runtime.h>

// ---------------------------------------------------------------------------
// B=4, C_IN=256, C=128, H=W=64, HW=4096
// output: [4,128,128,128] float32
// ---------------------------------------------------------------------------

#define F_RES1 0
#define F_RES2 (F_RES1 + 2097152)
#define F_SIM  (F_RES2 + 2097152)
#define F_DIFC (F_SIM  + 16384)
#define F_ABSD (F_DIFC + 4194304)
#define F_SIMP (F_ABSD + 2097152)
#define F_R    (F_SIMP + 524288)
#define F_B0B1 (F_R    + 2097152)
#define F_DIF  (F_B0B1 + 2097152)
#define F_INC  (F_DIF  + 2097152)
#define F_LOG  (F_INC  + 2097152)
#define F_ACAT (F_LOG  + 16777216)
#define F_FUSE (F_ACAT + 4194304)
#define F_TOTAL (F_FUSE + 2097152)

__device__ float g_scratch[F_TOTAL];

// ---------------------------------------------------------------------------
// High-throughput fp32 GEMM: tile 128x128, k-step 16, 256 threads, 8x8 micro.
// Double-buffered SMEM, float4 global loads, LDS.128 smem reads.
// aTrans==0: A row-major [M,K]. aTrans==1: A row-major [K,M] (M==multiple of 128).
// C[b,m,n] = sum_k A.B + bias[m]; if scale: relu->*scale[m]+off[m]; +resid.
// Requires M%128==0, N%128==0, K%16==0.
// ---------------------------------------------------------------------------
__global__ void __launch_bounds__(256, 2) gemm128_k(
    const float* __restrict__ A, const float* __restrict__ B, float* __restrict__ Cc,
    const float* __restrict__ bias, const float* __restrict__ scale,
    const float* __restrict__ off, const float* __restrict__ resid,
    int M, int N, int K,
    long long Abatch, long long Bbatch, long long Cbatch, long long Rbatch,
    int aTrans)
{
    __shared__ __align__(16) float As[2][16][128];
    __shared__ __align__(16) float Bs[2][16][128];
    const int b  = blockIdx.z;
    const int m0 = blockIdx.y * 128;
    const int n0 = blockIdx.x * 128;
    const float* Ab = A + (long long)b * Abatch;
    const float* Bb = B + (long long)b * Bbatch + n0;
    const int t  = threadIdx.x;
    const int tx = t & 15;
    const int ty = t >> 4;

    float acc[8][8];
#pragma unroll
    for (int i = 0; i < 8; i++)
#pragma unroll
        for (int j = 0; j < 8; j++) acc[i][j] = 0.f;

    float4 ra[2], rb[2];

    auto pref = [&](int k0) {
        if (aTrans == 0) {
#pragma unroll
            for (int r = 0; r < 2; r++) {
                int f = t + 256 * r, row = f >> 2, kq = f & 3;
                ra[r] = *(const float4*)&Ab[(long long)(m0 + row) * K + k0 + kq * 4];
            }
        } else {
#pragma unroll
            for (int r = 0; r < 2; r++) {
                int f = t + 256 * r, k = f >> 5, mq = f & 31;
                ra[r] = *(const float4*)&Ab[(long long)(k0 + k) * M + m0 + mq * 4];
            }
        }
#pragma unroll
        for (int r = 0; r < 2; r++) {
            int f = t + 256 * r, k = f >> 5, nq = f & 31;
            rb[r] = *(const float4*)&Bb[(long long)(k0 + k) * N + nq * 4];
        }
    };
    auto stob = [&](int buf) {
        if (aTrans == 0) {
#pragma unroll
            for (int r = 0; r < 2; r++) {
                int f = t + 256 * r, row = f >> 2, kq = f & 3;
                As[buf][kq * 4 + 0][row] = ra[r].x;
                As[buf][kq * 4 + 1][row] = ra[r].y;
                As[buf][kq * 4 + 2][row] = ra[r].z;
                As[buf][kq * 4 + 3][row] = ra[r].w;
            }
        } else {
#pragma unroll
            for (int r = 0; r < 2; r++) {
                int f = t + 256 * r, k = f >> 5, mq = f & 31;
                *(float4*)&As[buf][k][mq * 4] = ra[r];
            }
        }
#pragma unroll
        for (int r = 0; r < 2; r++) {
            int f = t + 256 * r, k = f >> 5, nq = f & 31;
            *(float4*)&Bs[buf][k][nq * 4] = rb[r];
        }
    };

    pref(0); stob(0); __syncthreads();
    int buf = 0;
    for (int k0 = 0; k0 < K; k0 += 16) {
        bool more = (k0 + 16) < K;
        if (more) pref(k0 + 16);
#pragma unroll
        for (int kk = 0; kk < 16; kk++) {
            float4 a0 = *(const float4*)&As[buf][kk][ty * 8];
            float4 a1 = *(const float4*)&As[buf][kk][ty * 8 + 4];
            float4 b0 = *(const float4*)&Bs[buf][kk][tx * 8];
            float4 b1 = *(const float4*)&Bs[buf][kk][tx * 8 + 4];
            float aa[8] = {a0.x, a0.y, a0.z, a0.w, a1.x, a1.y, a1.z, a1.w};
            float bb[8] = {b0.x, b0.y, b0.z, b0.w, b1.x, b1.y, b1.z, b1.w};
#pragma unroll
            for (int i = 0; i < 8; i++)
#pragma unroll
                for (int j = 0; j < 8; j++) acc[i][j] += aa[i] * bb[j];
        }
        if (more) { stob(buf ^ 1); __syncthreads(); buf ^= 1; }
    }

#pragma unroll
    for (int i = 0; i < 8; i++) {
        int m = m0 + ty * 8 + i;
        float bi = bias  ? bias[m]  : 0.f;
        float sc = scale ? scale[m] : 1.f;
        float of = off   ? off[m]   : 0.f;
        float* cp = Cc + (long long)b * Cbatch + (long long)m * N + n0 + tx * 8;
        const float* rp = resid ? (resid + (long long)b * Rbatch + (long long)m * N + n0 + tx * 8)
                                : nullptr;
        float v[8];
#pragma unroll
        for (int j = 0; j < 8; j++) {
            v[j] = acc[i][j] + bi;
            if (scale) v[j] = fmaxf(v[j], 0.f) * sc + of;
        }
        if (rp) {
            float4 r0 = *(const float4*)rp, r1 = *(const float4*)(rp + 4);
            v[0] += r0.x; v[1] += r0.y; v[2] += r0.z; v[3] += r0.w;
            v[4] += r1.x; v[5] += r1.y; v[6] += r1.z; v[7] += r1.w;
        }
        *(float4*)cp       = make_float4(v[0], v[1], v[2], v[3]);
        *(float4*)(cp + 4) = make_float4(v[4], v[5], v[6], v[7]);
    }
}

// ---------------------------------------------------------------------------
// Implicit-GEMM conv KSxKS (pad=KS/2) on [B,Cin,64,64], weights OIHW
// (naturally [Cout, Cin*KS*KS] row-major). Tile MT x 128 pixels, k-step 16.
// MT=128 -> 8x8 micro; MT=64 -> 4x8 micro. grid = (32, 1, B).
// ---------------------------------------------------------------------------
template <int KS, int MT>
__global__ void __launch_bounds__(256, 2) convig_k(
    const float* __restrict__ in, const float* __restrict__ w,
    const float* __restrict__ bias, const float* __restrict__ scale,
    const float* __restrict__ off,
    float* __restrict__ out, long long out_bstride, int Cin)
{
    constexpr int KS2 = KS * KS;
    constexpr int P   = KS / 2;
    constexpr int MR  = MT / 16;    // rows per thread
    constexpr int ALD = MT / 64;    // float4 A loads per thread
    __shared__ __align__(16) float As[2][16][MT];
    __shared__ __align__(16) float Bs[2][16][128];
    const int t  = threadIdx.x;
    const int tx = t & 15;
    const int ty = t >> 4;
    const int n0 = blockIdx.x * 128;
    const int b  = blockIdx.z;
    const float* inb = in + (long long)b * Cin * 4096;
    const int K = Cin * KS2;
    // B-load mapping: one k-row, 8 consecutive pixels per thread
    const int krow  = t >> 4;
    const int ng    = t & 15;
    const int nb    = n0 + ng * 8;
    const int ybase = nb >> 6;
    const int xbase = nb & 63;

    float acc[MR][8];
#pragma unroll
    for (int i = 0; i < MR; i++)
#pragma unroll
        for (int j = 0; j < 8; j++) acc[i][j] = 0.f;

    float rbv[8];
    float4 ra[ALD];

    auto pref = [&](int k0) {
        int k  = k0 + krow;
        int ci = k / KS2;
        int tap = k - ci * KS2;
        int dy = tap / KS - P, dx = tap % KS - P;
        int y  = ybase + dy;
        const float* ip = inb + (long long)ci * 4096 + y * 64;
        bool yok = ((unsigned)y < 64u);
#pragma unroll
        for (int j = 0; j < 8; j++) {
            int xx = xbase + j + dx;
            rbv[j] = (yok && (unsigned)xx < 64u) ? ip[xx] : 0.f;
        }
#pragma unroll
        for (int r = 0; r < ALD; r++) {
            int f = t + 256 * r, row = f >> 2, kq = f & 3;
            ra[r] = *(const float4*)&w[(long long)row * K + k0 + kq * 4];
        }
    };
    auto stob = [&](int buf) {
#pragma unroll
        for (int j = 0; j < 8; j++) Bs[buf][krow][ng * 8 + j] = rbv[j];
#pragma unroll
        for (int r = 0; r < ALD; r++) {
            int f = t + 256 * r, row = f >> 2, kq = f & 3;
            As[buf][kq * 4 + 0][row] = ra[r].x;
            As[buf][kq * 4 + 1][row] = ra[r].y;
            As[buf][kq * 4 + 2][row] = ra[r].z;
            As[buf][kq * 4 + 3][row] = ra[r].w;
        }
    };

    pref(0); stob(0); __syncthreads();
    int buf = 0;
    for (int k0 = 0; k0 < K; k0 += 16) {
        bool more = (k0 + 16) < K;
        if (more) pref(k0 + 16);
#pragma unroll
        for (int kk = 0; kk < 16; kk++) {
            float4 b0 = *(const float4*)&Bs[buf][kk][tx * 8];
            float4 b1 = *(const float4*)&Bs[buf][kk][tx * 8 + 4];
            float bb[8] = {b0.x, b0.y, b0.z, b0.w, b1.x, b1.y, b1.z, b1.w};
            float aa[MR];
            if (MR == 8) {
                float4 a0 = *(const float4*)&As[buf][kk][ty * 8];
                float4 a1 = *(const float4*)&As[buf][kk][ty * 8 + 4];
                aa[0] = a0.x; aa[1] = a0.y; aa[2] = a0.z; aa[3] = a0.w;
                aa[4] = a1.x; aa[5] = a1.y; aa[6] = a1.z; aa[7] = a1.w;
            } else {
                float4 a0 = *(const float4*)&As[buf][kk][ty * 4];
                aa[0] = a0.x; aa[1] = a0.y; aa[2] = a0.z; aa[3] = a0.w;
            }
#pragma unroll
            for (int i = 0; i < MR; i++)
#pragma unroll
                for (int j = 0; j < 8; j++) acc[i][j] += aa[i] * bb[j];
        }
        if (more) { stob(buf ^ 1); __syncthreads(); buf ^= 1; }
    }

#pragma unroll
    for (int i = 0; i < MR; i++) {
        int co = ty * MR + i;
        float bi = bias[co];
        float sc = scale ? scale[co] : 1.f;
        float of = off   ? off[co]   : 0.f;
        float* op = out + (long long)b * out_bstride + (long long)co * 4096 + n0 + tx * 8;
        float v[8];
#pragma unroll
        for (int j = 0; j < 8; j++) {
            v[j] = acc[i][j] + bi;
            if (scale) v[j] = fmaxf(v[j], 0.f) * sc + of;
        }
        *(float4*)op       = make_float4(v[0], v[1], v[2], v[3]);
        *(float4*)(op + 4) = make_float4(v[4], v[5], v[6], v[7]);
    }
}

// ---------------------------------------------------------------------------
// Cosine similarity over contiguous 128-float chunks. One warp per chunk.
// ---------------------------------------------------------------------------
__global__ void cos_k(const float* __restrict__ r1, const float* __restrict__ r2,
                      float* __restrict__ sim)
{
    int gid  = blockIdx.x * blockDim.x + threadIdx.x;
    int wid  = gid >> 5;
    int lane = gid & 31;
    if (wid >= 4 * 4096) return;
    const float* a = r1 + (long long)wid * 128;
    const float* c = r2 + (long long)wid * 128;
    float dot = 0.f, na = 0.f, nb = 0.f;
#pragma unroll
    for (int i = 0; i < 4; i++) {
        float x = a[lane + 32 * i], y = c[lane + 32 * i];
        dot += x * y; na += x * x; nb += y * y;
    }
#pragma unroll
    for (int o = 16; o; o >>= 1) {
        dot += __shfl_xor_sync(0xffffffffu, dot, o);
        na  += __shfl_xor_sync(0xffffffffu, na,  o);
        nb  += __shfl_xor_sync(0xffffffffu, nb,  o);
    }
    if (lane == 0)
        sim[wid] = dot / fmaxf(sqrtf(na) * sqrtf(nb), 1e-8f);
}

// ---------------------------------------------------------------------------
// dif1/dif2 (difcat [B,256,4096]) and |sim1-sim2| (absd [B,128,4096]).
// ---------------------------------------------------------------------------
__global__ void difsim_k(const float* __restrict__ r1, const float* __restrict__ r2,
                         const float* __restrict__ sim,
                         float* __restrict__ difcat, float* __restrict__ absd)
{
    __shared__ float f1s[32][33], f2s[32][33], ss[32];
    const int b  = blockIdx.z;
    const int c0 = blockIdx.y * 32;
    const int n0 = blockIdx.x * 32;
    const int t  = threadIdx.x;
    const int tx = t & 31, ty = t >> 5;
    const long long BS = 524288;
    const float* r1b = r1 + (long long)b * BS;
    const float* r2b = r2 + (long long)b * BS;
#pragma unroll
    for (int r = 0; r < 4; r++) {
        int n = ty + 8 * r;
        f1s[n][tx] = r1b[(long long)(n0 + n) * 128 + c0 + tx];
        f2s[n][tx] = r2b[(long long)(n0 + n) * 128 + c0 + tx];
    }
    if (t < 32) ss[t] = sim[b * 4096 + n0 + t];
    __syncthreads();
#pragma unroll
    for (int r = 0; r < 4; r++) {
        int c = c0 + ty + 8 * r;
        int n = n0 + tx;
        float rv1 = r1b[(long long)c * 4096 + n];
        float rv2 = r2b[(long long)c * 4096 + n];
        float s  = ss[tx];
        float f1 = f1s[tx][ty + 8 * r];
        float f2 = f2s[tx][ty + 8 * r];
        float omns = 1.f - s;
        long long bo = (long long)b * (256LL * 4096) + (long long)c * 4096 + n;
        difcat[bo]                = f1 * omns + rv1;
        difcat[bo + 128LL * 4096] = f2 * omns + rv2;
        absd[(long long)b * BS + (long long)c * 4096 + n] =
            fabsf((f1 - f2) * s + rv1 - rv2);
    }
}

// AvgPool2d(2,2): absd [B,128,64,64] -> simp [B,128,32,32]
__global__ void pool_k(const float* __restrict__ absd, float* __restrict__ simp)
{
    int i = blockIdx.x * 256 + threadIdx.x;
    if (i >= 524288) return;
    int wp = i & 31, hp = (i >> 5) & 31, bc = i >> 10;
    const float* a = absd + (long long)bc * 4096 + (hp * 2) * 64 + wp * 2;
    simp[i] = 0.25f * (a[0] + a[1] + a[64] + a[65]);
}

// Row softmax over 4096, in place; one block per row.
__global__ void softmax_k(float* __restrict__ logits)
{
    __shared__ float red[256];
    float* p = logits + (long long)blockIdx.x * 4096;
    const int t = threadIdx.x;
    float v[16];
    float mx = -1e30f;
#pragma unroll
    for (int i = 0; i < 16; i++) { v[i] = p[t + 256 * i]; mx = fmaxf(mx, v[i]); }
    red[t] = mx; __syncthreads();
    for (int o = 128; o; o >>= 1) {
        if (t < o) red[t] = fmaxf(red[t], red[t + o]);
        __syncthreads();
    }
    mx = red[0]; __syncthreads();
    float sum = 0.f;
#pragma unroll
    for (int i = 0; i < 16; i++) { v[i] = __expf(v[i] - mx); sum += v[i]; }
    red[t] = sum; __syncthreads();
    for (int o = 128; o; o >>= 1) {
        if (t < o) red[t] += red[t + o];
        __syncthreads();
    }
    float inv = 1.f / red[0];
#pragma unroll
    for (int i = 0; i < 16; i++) p[t + 256 * i] = v[i] * inv;
}

// Bilinear x2 upsample: [B,128,64,64] -> [B,128,128,128]
__global__ void resize_k(const float* __restrict__ in, float* __restrict__ out)
{
    long long i = (long long)blockIdx.x * 256 + threadIdx.x;
    if (i >= 8388608LL) return;
    int x = (int)(i & 127), y = (int)((i >> 7) & 127);
    long long bc = i >> 14;
    float sx = (x + 0.5f) * 0.5f - 0.5f;
    float sy = (y + 0.5f) * 0.5f - 0.5f;
    int x0 = (int)floorf(sx), y0 = (int)floorf(sy);
    float fx = sx - x0, fy = sy - y0;
    int x1 = min(x0 + 1, 63), y1 = min(y0 + 1, 63);
    x0 = max(x0, 0); y0 = max(y0, 0);
    const float* p = in + bc * 4096;
    float v = (1.f - fy) * ((1.f - fx) * p[y0 * 64 + x0] + fx * p[y0 * 64 + x1])
            +        fy  * ((1.f - fx) * p[y1 * 64 + x0] + fx * p[y1 * 64 + x1]);
    out[i] = v;
}

// ---------------------------------------------------------------------------
extern "C" void kernel_launch(void* const* d_in, const int* in_sizes, int n_in,
                              void* d_out, int out_size)
{
    (void)in_sizes; (void)n_in; (void)out_size;
    const float* t1      = (const float*)d_in[0];
    const float* t2      = (const float*)d_in[1];
    const float* t1_w    = (const float*)d_in[2];
    const float* t1_b    = (const float*)d_in[3];
    const float* t2_w    = (const float*)d_in[4];
    const float* t2_b    = (const float*)d_in[5];
    const float* df_res_w = (const float*)d_in[6];
    const float* df_res_b = (const float*)d_in[7];
    const float* df_res_s = (const float*)d_in[8];
    const float* df_res_o = (const float*)d_in[9];
    const float* df_b0_w = (const float*)d_in[10];
    const float* df_b0_b = (const float*)d_in[11];
    const float* df_b0_s = (const float*)d_in[12];
    const float* df_b0_o = (const float*)d_in[13];
    const float* df_b1_w = (const float*)d_in[14];
    const float* df_b1_b = (const float*)d_in[15];
    const float* df_b1_s = (const float*)d_in[16];
    const float* df_b1_o = (const float*)d_in[17];
    const float* df_fu_w = (const float*)d_in[18];
    const float* df_fu_b = (const float*)d_in[19];
    const float* df_fu_s = (const float*)d_in[20];
    const float* df_fu_o = (const float*)d_in[21];
    const float* br1_w   = (const float*)d_in[22];
    const float* br1_b   = (const float*)d_in[23];
    const float* br2_w   = (const float*)d_in[24];
    const float* br2_b   = (const float*)d_in[25];
    const float* fu_w    = (const float*)d_in[26];
    const float* fu_b    = (const float*)d_in[27];
    const float* fu_s    = (const float*)d_in[28];
    const float* fu_o    = (const float*)d_in[29];
    float* out = (float*)d_out;

    float* S;
    cudaGetSymbolAddress((void**)&S, g_scratch);
    float* res1   = S + F_RES1;
    float* res2   = S + F_RES2;
    float* sim    = S + F_SIM;
    float* difcat = S + F_DIFC;
    float* absd   = S + F_ABSD;
    float* simp   = S + F_SIMP;
    float* rbuf   = S + F_R;
    float* b0b1   = S + F_B0B1;
    float* dif    = S + F_DIF;
    float* inc    = S + F_INC;
    float* logits = S + F_LOG;
    float* acat   = S + F_ACAT;
    float* fuse   = S + F_FUSE;

    const long long S128 = 128LL * 4096;
    const long long S256 = 256LL * 4096;
    const long long SLOG = 1024LL * 4096;

    // 1. res1/res2 = 1x1 conv (256->128) + bias
    gemm128_k<<<dim3(32, 1, 4), 256>>>(t1_w, t1, res1, t1_b, nullptr, nullptr, nullptr,
                                       128, 4096, 256, 0, S256, S128, 0, 0);
    gemm128_k<<<dim3(32, 1, 4), 256>>>(t2_w, t2, res2, t2_b, nullptr, nullptr, nullptr,
                                       128, 4096, 256, 0, S256, S128, 0, 0);
    // 2. cosine similarity
    cos_k<<<2048, 256>>>(res1, res2, sim);
    // 3. dif1/dif2 + |sim1-sim2|
    difsim_k<<<dim3(128, 4, 4), 256>>>(res1, res2, sim, difcat, absd);
    // 4. avgpool -> simp (== attn)
    pool_k<<<2048, 256>>>(absd, simp);
    // 5. r = stdconv 1x1 (256->128)
    gemm128_k<<<dim3(32, 1, 4), 256>>>(df_res_w, difcat, rbuf, df_res_b, df_res_s, df_res_o,
                                       nullptr, 128, 4096, 256, 0, S256, S128, 0, 0);
    // 6/7. b0 (3x3, 128->64) and b1 (5x5, 128->64) into cat buffer
    convig_k<3, 64><<<dim3(32, 1, 4), 256>>>(rbuf, df_b0_w, df_b0_b, df_b0_s, df_b0_o,
                                             b0b1, S128, 128);
    convig_k<5, 64><<<dim3(32, 1, 4), 256>>>(rbuf, df_b1_w, df_b1_b, df_b1_s, df_b1_o,
                                             b0b1 + 64LL * 4096, S128, 128);
    // 8. dif = stdconv 1x1 (128->128) + r
    gemm128_k<<<dim3(32, 1, 4), 256>>>(df_fu_w, b0b1, dif, df_fu_b, df_fu_s, df_fu_o,
                                       rbuf, 128, 4096, 128, 0, S128, S128, S128, 0);
    // --- branch 1: inc1 = conv3x3(dif)+bias; attention; a1 -> acat[:, :128] ---
    convig_k<3, 128><<<dim3(32, 1, 4), 256>>>(dif, br1_w, br1_b, nullptr, nullptr,
                                              inc, S128, 128);
    gemm128_k<<<dim3(32, 8, 4), 256>>>(simp, inc, logits, nullptr, nullptr, nullptr, nullptr,
                                       1024, 4096, 128, 131072, S128, SLOG, 0, 0);
    softmax_k<<<4096, 256>>>(logits);
    gemm128_k<<<dim3(32, 1, 4), 256>>>(simp, logits, acat, nullptr, nullptr, nullptr,
                                       inc, 128, 4096, 1024, 131072, SLOG, S256, S128, 1);
    // --- branch 2: inc2 = conv5x5(dif); attention; a2 -> acat[:, 128:] ---
    convig_k<5, 128><<<dim3(32, 1, 4), 256>>>(dif, br2_w, br2_b, nullptr, nullptr,
                                              inc, S128, 128);
    gemm128_k<<<dim3(32, 8, 4), 256>>>(simp, inc, logits, nullptr, nullptr, nullptr, nullptr,
                                       1024, 4096, 128, 131072, S128, SLOG, 0, 0);
    softmax_k<<<4096, 256>>>(logits);
    gemm128_k<<<dim3(32, 1, 4), 256>>>(simp, logits, acat + 128LL * 4096, nullptr, nullptr, nullptr,
                                       inc, 128, 4096, 1024, 131072, SLOG, S256, S128, 1);
    // 14. fused = stdconv 1x1 (256->128) + dif
    gemm128_k<<<dim3(32, 1, 4), 256>>>(fu_w, acat, fuse, fu_b, fu_s, fu_o,
                                       dif, 128, 4096, 256, 0, S256, S128, S128, 0);
    // 15. bilinear x2 upsample to output
    resize_k<<<32768, 256>>>(fuse, out);
}

// round 6
// speedup vs baseline: 1.3482x; 1.0651x over previous
#include <cuda_runtime.h>
#include <cuda_bf16.h>
#include <cstdint>

// ===========================================================================
// B=4, C_IN=256, C=128, H=W=64, HW=4096. out [4,128,128,128] f32.
// Attention pairs on mma.sync bf16 HMMA (2-term split, K'=3K); rest scalar.
// ===========================================================================

#define F_RES1 0LL
#define F_RES2 (F_RES1 + 2097152)
#define F_SIM  (F_RES2 + 2097152)
#define F_DIFC (F_SIM  + 16384)
#define F_ABSD (F_DIFC + 4194304)
#define F_SIMP (F_ABSD + 2097152)
#define F_R    (F_SIMP + 524288)
#define F_B0B1 (F_R    + 2097152)
#define F_DIF  (F_B0B1 + 2097152)
#define F_INC  (F_DIF  + 2097152)
#define F_LOG  (F_INC  + 2097152)      /* logitsT [B,4096,1024] */
#define F_ACAT (F_LOG  + 16777216)
#define F_FUSE (F_ACAT + 4194304)
#define F_PAR  (F_FUSE + 2097152)
#define F_TOTAL (F_PAR + 8192)

__device__ float g_scratch[F_TOTAL];

#define G_ATTN3  0LL                       /* [B,1024,384]  */
#define G_INCT3  1572864LL                 /* [B,4096,384]  */
#define G_ATTNT3 7864320LL                 /* [B,128,3072]  */
#define G_AT3    9437184LL                 /* [B,4096,3072] */
#define G_TOTAL  59768832LL

__device__ __align__(256) __nv_bfloat16 g_bf[G_TOTAL];

// ===========================================================================
// wm_gemm: warp-level HMMA bf16 GEMM.
// C[b, m, n] = sum_k A3[b?][m,k] * B3[b][n,k]  (+ resid), fp32 accum.
// A3 [Mtot,Kp], B3 [Ntot,Kp] bf16 row-major (k contiguous), Kp % 32 == 0.
// Block tile 128x128, 8 warps (warp tile 32m x 64n), k-chunk 32, dbl-buffered.
// grid = (N/128, M/128, B), 256 threads.
// ===========================================================================
__global__ void __launch_bounds__(256) wm_gemm(
    const __nv_bfloat16* __restrict__ A3, const __nv_bfloat16* __restrict__ B3,
    float* __restrict__ C, const float* __restrict__ resid,
    int Kp, int Ncols,
    long long Abs, long long Bbs, long long Cbs, long long Rbs)
{
    __shared__ __align__(16) __nv_bfloat16 As[2][128][40];
    __shared__ __align__(16) __nv_bfloat16 Bs[2][128][40];
    const int t    = threadIdx.x;
    const int lane = t & 31;
    const int wid  = t >> 5;
    const int wm   = wid & 3;            // 4 warps along m
    const int wn   = wid >> 2;           // 2 warps along n
    const int g    = lane >> 2;          // group id 0..7
    const int tig  = lane & 3;           // thread-in-group
    const int b  = blockIdx.z;
    const int m0 = blockIdx.y * 128;
    const int n0 = blockIdx.x * 128;
    const __nv_bfloat16* Ab = A3 + (long long)b * Abs + (long long)m0 * Kp;
    const __nv_bfloat16* Bb = B3 + (long long)b * Bbs + (long long)n0 * Kp;

    float acc[2][8][4];
#pragma unroll
    for (int i = 0; i < 2; i++)
#pragma unroll
        for (int j = 0; j < 8; j++)
#pragma unroll
            for (int r = 0; r < 4; r++) acc[i][j][r] = 0.f;

    uint4 ra[2], rb[2];
    auto pref = [&](int k0) {
#pragma unroll
        for (int r = 0; r < 2; r++) {
            int f = t + 256 * r, row = f >> 2, kq = f & 3;
            ra[r] = *(const uint4*)(Ab + (long long)row * Kp + k0 + kq * 8);
            rb[r] = *(const uint4*)(Bb + (long long)row * Kp + k0 + kq * 8);
        }
    };
    auto stob = [&](int buf) {
#pragma unroll
        for (int r = 0; r < 2; r++) {
            int f = t + 256 * r, row = f >> 2, kq = f & 3;
            *(uint4*)&As[buf][row][kq * 8] = ra[r];
            *(uint4*)&Bs[buf][row][kq * 8] = rb[r];
        }
    };

    pref(0); stob(0); __syncthreads();
    const int nch = Kp >> 5;
    for (int c = 0; c < nch; c++) {
        const int buf = c & 1;
        const bool more = (c + 1) < nch;
        if (more) pref((c + 1) << 5);
#pragma unroll
        for (int ks = 0; ks < 2; ks++) {
            const int kb = ks * 16;
            uint32_t afr[2][4];
#pragma unroll
            for (int i = 0; i < 2; i++) {
                int row = wm * 32 + i * 16;
                afr[i][0] = *(const uint32_t*)&As[buf][row + g][kb + tig * 2];
                afr[i][1] = *(const uint32_t*)&As[buf][row + g + 8][kb + tig * 2];
                afr[i][2] = *(const uint32_t*)&As[buf][row + g][kb + tig * 2 + 8];
                afr[i][3] = *(const uint32_t*)&As[buf][row + g + 8][kb + tig * 2 + 8];
            }
            uint32_t bfr[8][2];
#pragma unroll
            for (int j = 0; j < 8; j++) {
                int nrow = wn * 64 + j * 8 + g;
                bfr[j][0] = *(const uint32_t*)&Bs[buf][nrow][kb + tig * 2];
                bfr[j][1] = *(const uint32_t*)&Bs[buf][nrow][kb + tig * 2 + 8];
            }
#pragma unroll
            for (int i = 0; i < 2; i++)
#pragma unroll
                for (int j = 0; j < 8; j++)
                    asm volatile(
                        "mma.sync.aligned.m16n8k16.row.col.f32.bf16.bf16.f32 "
                        "{%0,%1,%2,%3}, {%4,%5,%6,%7}, {%8,%9}, {%0,%1,%2,%3};"
                        : "+f"(acc[i][j][0]), "+f"(acc[i][j][1]),
                          "+f"(acc[i][j][2]), "+f"(acc[i][j][3])
                        : "r"(afr[i][0]), "r"(afr[i][1]), "r"(afr[i][2]), "r"(afr[i][3]),
                          "r"(bfr[j][0]), "r"(bfr[j][1]));
        }
        if (more) { stob(buf ^ 1); __syncthreads(); }
    }

    float* Cb = C + (long long)b * Cbs;
    const float* Rb = resid ? resid + (long long)b * Rbs : nullptr;
#pragma unroll
    for (int i = 0; i < 2; i++) {
        int row0 = m0 + wm * 32 + i * 16 + g;
#pragma unroll
        for (int j = 0; j < 8; j++) {
            int col = n0 + wn * 64 + j * 8 + tig * 2;
            float2 v0 = make_float2(acc[i][j][0], acc[i][j][1]);
            float2 v1 = make_float2(acc[i][j][2], acc[i][j][3]);
            long long o0 = (long long)row0 * Ncols + col;
            long long o1 = (long long)(row0 + 8) * Ncols + col;
            if (Rb) {
                float2 r0 = *(const float2*)(Rb + o0);
                float2 r1 = *(const float2*)(Rb + o1);
                v0.x += r0.x; v0.y += r0.y; v1.x += r1.x; v1.y += r1.y;
            }
            *(float2*)(Cb + o0) = v0;
            *(float2*)(Cb + o1) = v1;
        }
    }
}

// --------- split helpers ----------------------------------------------------
__device__ __forceinline__ void bsplit(float x, __nv_bfloat16& h, __nv_bfloat16& l) {
    h = __float2bfloat16(x);
    l = __float2bfloat16(x - __bfloat162float(h));
}

// attn3: simp [B*1024,128] f32 -> [B,1024,384] bf16, pattern B (hi,hi,lo)
__global__ void split3row_k(const float* __restrict__ in, __nv_bfloat16* __restrict__ out)
{
    int i = blockIdx.x * 256 + threadIdx.x;      // 4*1024*128
    float x = in[i];
    __nv_bfloat16 h, l; bsplit(x, h, l);
    long long row = i >> 7; int c = i & 127;
    __nv_bfloat16* o = out + row * 384 + c;
    o[0] = h; o[128] = h; o[256] = l;
}

// transpose+split: in [B,R,Ncol] f32 -> out [B,Ncol,3R] bf16, pattern A (hi,lo,hi)
__global__ void tsplit3_k(const float* __restrict__ in, __nv_bfloat16* __restrict__ out,
                          int R, int Ncol)
{
    __shared__ float tile[32][33];
    const int b = blockIdx.z, r0 = blockIdx.y * 32, n0 = blockIdx.x * 32;
    const int tx = threadIdx.x & 31, ty = threadIdx.x >> 5;
    const float* ib = in + (long long)b * R * Ncol;
#pragma unroll
    for (int p = 0; p < 4; p++)
        tile[ty + 8 * p][tx] = ib[(long long)(r0 + ty + 8 * p) * Ncol + n0 + tx];
    __syncthreads();
    __nv_bfloat16* ob = out + (long long)b * Ncol * 3 * R;
#pragma unroll
    for (int p = 0; p < 4; p++) {
        int n = n0 + ty + 8 * p, r = r0 + tx;
        float x = tile[tx][ty + 8 * p];
        __nv_bfloat16 h, l; bsplit(x, h, l);
        __nv_bfloat16* o = ob + (long long)n * 3 * R;
        o[r] = h; o[R + r] = l; o[2 * R + r] = h;
    }
}

// column softmax stats over logitsT [B,4096,1024]: per (b,tok) max & 1/sum
__global__ void colstat_k(const float* __restrict__ lt,
                          float* __restrict__ cmax, float* __restrict__ csum)
{
    __shared__ float smx[16][65], ssm[16][65];
    const int b = blockIdx.y;
    const int c = threadIdx.x & 63, g = threadIdx.x >> 6;
    const int col = blockIdx.x * 64 + c;
    const float* p = lt + (long long)b * 4194304 + col;
    float mx = -1e30f, sm = 0.f;
    for (int m = g; m < 4096; m += 16) {
        float x = p[(long long)m * 1024];
        float nm = fmaxf(mx, x);
        sm = sm * __expf(mx - nm) + __expf(x - nm);
        mx = nm;
    }
    smx[g][c] = mx; ssm[g][c] = sm;
    __syncthreads();
    if (g == 0) {
        float MX = smx[0][c], SM = ssm[0][c];
#pragma unroll
        for (int k = 1; k < 16; k++) {
            float m2 = smx[k][c], s2 = ssm[k][c];
            float nm = fmaxf(MX, m2);
            SM = SM * __expf(MX - nm) + s2 * __expf(m2 - nm);
            MX = nm;
        }
        cmax[b * 1024 + col] = MX;
        csum[b * 1024 + col] = 1.f / SM;
    }
}

// normalize + split -> aT3 [B,4096,3072], pattern B (hi,hi,lo)
__global__ void colwrite_k(const float* __restrict__ lt,
                           const float* __restrict__ cmax, const float* __restrict__ csum,
                           __nv_bfloat16* __restrict__ out)
{
    long long i = (long long)blockIdx.x * 256 + threadIdx.x;   // 16,777,216
    int tcol = (int)(i & 1023);
    long long bm = i >> 10;           // b*4096 + m
    int b = (int)(bm >> 12);
    float e = __expf(lt[i] - cmax[b * 1024 + tcol]) * csum[b * 1024 + tcol];
    __nv_bfloat16 h, l; bsplit(e, h, l);
    __nv_bfloat16* o = out + bm * 3072 + tcol;
    o[0] = h; o[1024] = h; o[2048] = l;
}

// ===========================================================================
// scalar fp32 kernels (proven in round 3)
// ===========================================================================
__global__ void __launch_bounds__(256, 2) gemm128_k(
    const float* __restrict__ A, const float* __restrict__ B, float* __restrict__ Cc,
    const float* __restrict__ bias, const float* __restrict__ scale,
    const float* __restrict__ off, const float* __restrict__ resid,
    int M, int N, int K,
    long long Abatch, long long Bbatch, long long Cbatch, long long Rbatch)
{
    __shared__ __align__(16) float As[2][16][128];
    __shared__ __align__(16) float Bs[2][16][128];
    const int b  = blockIdx.z;
    const int m0 = blockIdx.y * 128;
    const int n0 = blockIdx.x * 128;
    const float* Ab = A + (long long)b * Abatch;
    const float* Bb = B + (long long)b * Bbatch + n0;
    const int t  = threadIdx.x;
    const int tx = t & 15;
    const int ty = t >> 4;
    float acc[8][8];
#pragma unroll
    for (int i = 0; i < 8; i++)
#pragma unroll
        for (int j = 0; j < 8; j++) acc[i][j] = 0.f;
    float4 ra[2], rb[2];
    auto pref = [&](int k0) {
#pragma unroll
        for (int r = 0; r < 2; r++) {
            int f = t + 256 * r, row = f >> 2, kq = f & 3;
            ra[r] = *(const float4*)&Ab[(long long)(m0 + row) * K + k0 + kq * 4];
        }
#pragma unroll
        for (int r = 0; r < 2; r++) {
            int f = t + 256 * r, k = f >> 5, nq = f & 31;
            rb[r] = *(const float4*)&Bb[(long long)(k0 + k) * N + nq * 4];
        }
    };
    auto stob = [&](int buf) {
#pragma unroll
        for (int r = 0; r < 2; r++) {
            int f = t + 256 * r, row = f >> 2, kq = f & 3;
            As[buf][kq * 4 + 0][row] = ra[r].x;
            As[buf][kq * 4 + 1][row] = ra[r].y;
            As[buf][kq * 4 + 2][row] = ra[r].z;
            As[buf][kq * 4 + 3][row] = ra[r].w;
        }
#pragma unroll
        for (int r = 0; r < 2; r++) {
            int f = t + 256 * r, k = f >> 5, nq = f & 31;
            *(float4*)&Bs[buf][k][nq * 4] = rb[r];
        }
    };
    pref(0); stob(0); __syncthreads();
    int buf = 0;
    for (int k0 = 0; k0 < K; k0 += 16) {
        bool more = (k0 + 16) < K;
        if (more) pref(k0 + 16);
#pragma unroll
        for (int kk = 0; kk < 16; kk++) {
            float4 a0 = *(const float4*)&As[buf][kk][ty * 8];
            float4 a1 = *(const float4*)&As[buf][kk][ty * 8 + 4];
            float4 b0 = *(const float4*)&Bs[buf][kk][tx * 8];
            float4 b1 = *(const float4*)&Bs[buf][kk][tx * 8 + 4];
            float aa[8] = {a0.x, a0.y, a0.z, a0.w, a1.x, a1.y, a1.z, a1.w};
            float bb[8] = {b0.x, b0.y, b0.z, b0.w, b1.x, b1.y, b1.z, b1.w};
#pragma unroll
            for (int i = 0; i < 8; i++)
#pragma unroll
                for (int j = 0; j < 8; j++) acc[i][j] += aa[i] * bb[j];
        }
        if (more) { stob(buf ^ 1); __syncthreads(); buf ^= 1; }
    }
#pragma unroll
    for (int i = 0; i < 8; i++) {
        int m = m0 + ty * 8 + i;
        float bi = bias  ? bias[m]  : 0.f;
        float sc = scale ? scale[m] : 1.f;
        float of = off   ? off[m]   : 0.f;
        float* cp = Cc + (long long)b * Cbatch + (long long)m * N + n0 + tx * 8;
        const float* rp = resid ? (resid + (long long)b * Rbatch + (long long)m * N + n0 + tx * 8)
                                : nullptr;
        float v[8];
#pragma unroll
        for (int j = 0; j < 8; j++) {
            v[j] = acc[i][j] + bi;
            if (scale) v[j] = fmaxf(v[j], 0.f) * sc + of;
        }
        if (rp) {
            float4 r0 = *(const float4*)rp, r1 = *(const float4*)(rp + 4);
            v[0] += r0.x; v[1] += r0.y; v[2] += r0.z; v[3] += r0.w;
            v[4] += r1.x; v[5] += r1.y; v[6] += r1.z; v[7] += r1.w;
        }
        *(float4*)cp       = make_float4(v[0], v[1], v[2], v[3]);
        *(float4*)(cp + 4) = make_float4(v[4], v[5], v[6], v[7]);
    }
}

template <int KS, int MT>
__global__ void __launch_bounds__(256, 2) convig_k(
    const float* __restrict__ in, const float* __restrict__ w,
    const float* __restrict__ bias, const float* __restrict__ scale,
    const float* __restrict__ off,
    float* __restrict__ out, long long out_bstride, int Cin)
{
    constexpr int KS2 = KS * KS;
    constexpr int P   = KS / 2;
    constexpr int MR  = MT / 16;
    constexpr int ALD = MT / 64;
    __shared__ __align__(16) float As[2][16][MT];
    __shared__ __align__(16) float Bs[2][16][128];
    const int t  = threadIdx.x;
    const int tx = t & 15;
    const int ty = t >> 4;
    const int n0 = blockIdx.x * 128;
    const int b  = blockIdx.z;
    const float* inb = in + (long long)b * Cin * 4096;
    const int K = Cin * KS2;
    const int krow  = t >> 4;
    const int ng    = t & 15;
    const int nb    = n0 + ng * 8;
    const int ybase = nb >> 6;
    const int xbase = nb & 63;
    float acc[MR][8];
#pragma unroll
    for (int i = 0; i < MR; i++)
#pragma unroll
        for (int j = 0; j < 8; j++) acc[i][j] = 0.f;
    float rbv[8];
    float4 ra[ALD];
    auto pref = [&](int k0) {
        int k  = k0 + krow;
        int ci = k / KS2;
        int tap = k - ci * KS2;
        int dy = tap / KS - P, dx = tap % KS - P;
        int y  = ybase + dy;
        const float* ip = inb + (long long)ci * 4096 + y * 64;
        bool yok = ((unsigned)y < 64u);
#pragma unroll
        for (int j = 0; j < 8; j++) {
            int xx = xbase + j + dx;
            rbv[j] = (yok && (unsigned)xx < 64u) ? ip[xx] : 0.f;
        }
#pragma unroll
        for (int r = 0; r < ALD; r++) {
            int f = t + 256 * r, row = f >> 2, kq = f & 3;
            ra[r] = *(const float4*)&w[(long long)row * K + k0 + kq * 4];
        }
    };
    auto stob = [&](int buf) {
#pragma unroll
        for (int j = 0; j < 8; j++) Bs[buf][krow][ng * 8 + j] = rbv[j];
#pragma unroll
        for (int r = 0; r < ALD; r++) {
            int f = t + 256 * r, row = f >> 2, kq = f & 3;
            As[buf][kq * 4 + 0][row] = ra[r].x;
            As[buf][kq * 4 + 1][row] = ra[r].y;
            As[buf][kq * 4 + 2][row] = ra[r].z;
            As[buf][kq * 4 + 3][row] = ra[r].w;
        }
    };
    pref(0); stob(0); __syncthreads();
    int buf = 0;
    for (int k0 = 0; k0 < K; k0 += 16) {
        bool more = (k0 + 16) < K;
        if (more) pref(k0 + 16);
#pragma unroll
        for (int kk = 0; kk < 16; kk++) {
            float4 b0 = *(const float4*)&Bs[buf][kk][tx * 8];
            float4 b1 = *(const float4*)&Bs[buf][kk][tx * 8 + 4];
            float bb[8] = {b0.x, b0.y, b0.z, b0.w, b1.x, b1.y, b1.z, b1.w};
            float aa[MR];
            if (MR == 8) {
                float4 a0 = *(const float4*)&As[buf][kk][ty * 8];
                float4 a1 = *(const float4*)&As[buf][kk][ty * 8 + 4];
                aa[0] = a0.x; aa[1] = a0.y; aa[2] = a0.z; aa[3] = a0.w;
                aa[4] = a1.x; aa[5] = a1.y; aa[6] = a1.z; aa[7] = a1.w;
            } else {
                float4 a0 = *(const float4*)&As[buf][kk][ty * 4];
                aa[0] = a0.x; aa[1] = a0.y; aa[2] = a0.z; aa[3] = a0.w;
            }
#pragma unroll
            for (int i = 0; i < MR; i++)
#pragma unroll
                for (int j = 0; j < 8; j++) acc[i][j] += aa[i] * bb[j];
        }
        if (more) { stob(buf ^ 1); __syncthreads(); buf ^= 1; }
    }
#pragma unroll
    for (int i = 0; i < MR; i++) {
        int co = ty * MR + i;
        float bi = bias[co];
        float sc = scale ? scale[co] : 1.f;
        float of = off   ? off[co]   : 0.f;
        float* op = out + (long long)b * out_bstride + (long long)co * 4096 + n0 + tx * 8;
        float v[8];
#pragma unroll
        for (int j = 0; j < 8; j++) {
            v[j] = acc[i][j] + bi;
            if (scale) v[j] = fmaxf(v[j], 0.f) * sc + of;
        }
        *(float4*)op       = make_float4(v[0], v[1], v[2], v[3]);
        *(float4*)(op + 4) = make_float4(v[4], v[5], v[6], v[7]);
    }
}

__global__ void cos_k(const float* __restrict__ r1, const float* __restrict__ r2,
                      float* __restrict__ sim)
{
    int gid  = blockIdx.x * blockDim.x + threadIdx.x;
    int wid  = gid >> 5;
    int lane = gid & 31;
    if (wid >= 4 * 4096) return;
    const float* a = r1 + (long long)wid * 128;
    const float* c = r2 + (long long)wid * 128;
    float dot = 0.f, na = 0.f, nb = 0.f;
#pragma unroll
    for (int i = 0; i < 4; i++) {
        float x = a[lane + 32 * i], y = c[lane + 32 * i];
        dot += x * y; na += x * x; nb += y * y;
    }
#pragma unroll
    for (int o = 16; o; o >>= 1) {
        dot += __shfl_xor_sync(0xffffffffu, dot, o);
        na  += __shfl_xor_sync(0xffffffffu, na,  o);
        nb  += __shfl_xor_sync(0xffffffffu, nb,  o);
    }
    if (lane == 0)
        sim[wid] = dot / fmaxf(sqrtf(na) * sqrtf(nb), 1e-8f);
}

__global__ void difsim_k(const float* __restrict__ r1, const float* __restrict__ r2,
                         const float* __restrict__ sim,
                         float* __restrict__ difcat, float* __restrict__ absd)
{
    __shared__ float f1s[32][33], f2s[32][33], ss[32];
    const int b  = blockIdx.z;
    const int c0 = blockIdx.y * 32;
    const int n0 = blockIdx.x * 32;
    const int t  = threadIdx.x;
    const int tx = t & 31, ty = t >> 5;
    const long long BS = 524288;
    const float* r1b = r1 + (long long)b * BS;
    const float* r2b = r2 + (long long)b * BS;
#pragma unroll
    for (int r = 0; r < 4; r++) {
        int n = ty + 8 * r;
        f1s[n][tx] = r1b[(long long)(n0 + n) * 128 + c0 + tx];
        f2s[n][tx] = r2b[(long long)(n0 + n) * 128 + c0 + tx];
    }
    if (t < 32) ss[t] = sim[b * 4096 + n0 + t];
    __syncthreads();
#pragma unroll
    for (int r = 0; r < 4; r++) {
        int c = c0 + ty + 8 * r;
        int n = n0 + tx;
        float rv1 = r1b[(long long)c * 4096 + n];
        float rv2 = r2b[(long long)c * 4096 + n];
        float s  = ss[tx];
        float f1 = f1s[tx][ty + 8 * r];
        float f2 = f2s[tx][ty + 8 * r];
        float omns = 1.f - s;
        long long bo = (long long)b * (256LL * 4096) + (long long)c * 4096 + n;
        difcat[bo]                = f1 * omns + rv1;
        difcat[bo + 128LL * 4096] = f2 * omns + rv2;
        absd[(long long)b * BS + (long long)c * 4096 + n] =
            fabsf((f1 - f2) * s + rv1 - rv2);
    }
}

__global__ void pool_k(const float* __restrict__ absd, float* __restrict__ simp)
{
    int i = blockIdx.x * 256 + threadIdx.x;
    if (i >= 524288) return;
    int wp = i & 31, hp = (i >> 5) & 31, bc = i >> 10;
    const float* a = absd + (long long)bc * 4096 + (hp * 2) * 64 + wp * 2;
    simp[i] = 0.25f * (a[0] + a[1] + a[64] + a[65]);
}

__global__ void resize_k(const float* __restrict__ in, float* __restrict__ out)
{
    long long i = (long long)blockIdx.x * 256 + threadIdx.x;
    if (i >= 8388608LL) return;
    int x = (int)(i & 127), y = (int)((i >> 7) & 127);
    long long bc = i >> 14;
    float sx = (x + 0.5f) * 0.5f - 0.5f;
    float sy = (y + 0.5f) * 0.5f - 0.5f;
    int x0 = (int)floorf(sx), y0 = (int)floorf(sy);
    float fx = sx - x0, fy = sy - y0;
    int x1 = min(x0 + 1, 63), y1 = min(y0 + 1, 63);
    x0 = max(x0, 0); y0 = max(y0, 0);
    const float* p = in + bc * 4096;
    float v = (1.f - fy) * ((1.f - fx) * p[y0 * 64 + x0] + fx * p[y0 * 64 + x1])
            +        fy  * ((1.f - fx) * p[y1 * 64 + x0] + fx * p[y1 * 64 + x1]);
    out[i] = v;
}

// ---------------------------------------------------------------------------
extern "C" void kernel_launch(void* const* d_in, const int* in_sizes, int n_in,
                              void* d_out, int out_size)
{
    (void)in_sizes; (void)n_in; (void)out_size;
    const float* t1      = (const float*)d_in[0];
    const float* t2      = (const float*)d_in[1];
    const float* t1_w    = (const float*)d_in[2];
    const float* t1_b    = (const float*)d_in[3];
    const float* t2_w    = (const float*)d_in[4];
    const float* t2_b    = (const float*)d_in[5];
    const float* df_res_w = (const float*)d_in[6];
    const float* df_res_b = (const float*)d_in[7];
    const float* df_res_s = (const float*)d_in[8];
    const float* df_res_o = (const float*)d_in[9];
    const float* df_b0_w = (const float*)d_in[10];
    const float* df_b0_b = (const float*)d_in[11];
    const float* df_b0_s = (const float*)d_in[12];
    const float* df_b0_o = (const float*)d_in[13];
    const float* df_b1_w = (const float*)d_in[14];
    const float* df_b1_b = (const float*)d_in[15];
    const float* df_b1_s = (const float*)d_in[16];
    const float* df_b1_o = (const float*)d_in[17];
    const float* df_fu_w = (const float*)d_in[18];
    const float* df_fu_b = (const float*)d_in[19];
    const float* df_fu_s = (const float*)d_in[20];
    const float* df_fu_o = (const float*)d_in[21];
    const float* br1_w   = (const float*)d_in[22];
    const float* br1_b   = (const float*)d_in[23];
    const float* br2_w   = (const float*)d_in[24];
    const float* br2_b   = (const float*)d_in[25];
    const float* fu_w    = (const float*)d_in[26];
    const float* fu_b    = (const float*)d_in[27];
    const float* fu_s    = (const float*)d_in[28];
    const float* fu_o    = (const float*)d_in[29];
    float* out = (float*)d_out;

    float* S;
    cudaGetSymbolAddress((void**)&S, g_scratch);
    __nv_bfloat16* G;
    cudaGetSymbolAddress((void**)&G, g_bf);

    float* res1    = S + F_RES1;
    float* res2    = S + F_RES2;
    float* sim     = S + F_SIM;
    float* difcat  = S + F_DIFC;
    float* absd    = S + F_ABSD;
    float* simp    = S + F_SIMP;
    float* rbuf    = S + F_R;
    float* b0b1    = S + F_B0B1;
    float* dif     = S + F_DIF;
    float* inc     = S + F_INC;
    float* logitsT = S + F_LOG;
    float* acat    = S + F_ACAT;
    float* fuse    = S + F_FUSE;
    float* cmax    = S + F_PAR;
    float* csum    = S + F_PAR + 4096;
    __nv_bfloat16* attn3  = G + G_ATTN3;
    __nv_bfloat16* incT3  = G + G_INCT3;
    __nv_bfloat16* attnT3 = G + G_ATTNT3;
    __nv_bfloat16* aT3    = G + G_AT3;

    const long long S128 = 128LL * 4096;
    const long long S256 = 256LL * 4096;

    // 1. res1/res2 = 1x1 conv (256->128) + bias
    gemm128_k<<<dim3(32, 1, 4), 256>>>(t1_w, t1, res1, t1_b, nullptr, nullptr, nullptr,
                                       128, 4096, 256, 0, S256, S128, 0);
    gemm128_k<<<dim3(32, 1, 4), 256>>>(t2_w, t2, res2, t2_b, nullptr, nullptr, nullptr,
                                       128, 4096, 256, 0, S256, S128, 0);
    // 2-4. cosine, dif mixing, avgpool
    cos_k<<<2048, 256>>>(res1, res2, sim);
    difsim_k<<<dim3(128, 4, 4), 256>>>(res1, res2, sim, difcat, absd);
    pool_k<<<2048, 256>>>(absd, simp);
    // attn operand prep (once)
    split3row_k<<<2048, 256>>>(simp, attn3);
    tsplit3_k<<<dim3(4, 32, 4), 256>>>(simp, attnT3, 1024, 128);
    // 5. r = stdconv 1x1 (256->128)
    gemm128_k<<<dim3(32, 1, 4), 256>>>(df_res_w, difcat, rbuf, df_res_b, df_res_s, df_res_o,
                                       nullptr, 128, 4096, 256, 0, S256, S128, 0);
    // 6/7. inception branches 3x3 / 5x5 (128->64 each)
    convig_k<3, 64><<<dim3(32, 1, 4), 256>>>(rbuf, df_b0_w, df_b0_b, df_b0_s, df_b0_o,
                                             b0b1, S128, 128);
    convig_k<5, 64><<<dim3(32, 1, 4), 256>>>(rbuf, df_b1_w, df_b1_b, df_b1_s, df_b1_o,
                                             b0b1 + 64LL * 4096, S128, 128);
    // 8. dif = stdconv 1x1 (128->128) + r
    gemm128_k<<<dim3(32, 1, 4), 256>>>(df_fu_w, b0b1, dif, df_fu_b, df_fu_s, df_fu_o,
                                       rbuf, 128, 4096, 128, 0, S128, S128, S128);
    // --- attention branches (HMMA) ---
    for (int br = 0; br < 2; br++) {
        if (br == 0)
            convig_k<3, 128><<<dim3(32, 1, 4), 256>>>(dif, br1_w, br1_b, nullptr, nullptr,
                                                      inc, S128, 128);
        else
            convig_k<5, 128><<<dim3(32, 1, 4), 256>>>(dif, br2_w, br2_b, nullptr, nullptr,
                                                      inc, S128, 128);
        tsplit3_k<<<dim3(128, 4, 4), 256>>>(inc, incT3, 128, 4096);
        // logitsT[b, pix, tok] = incT . attn
        wm_gemm<<<dim3(8, 32, 4), 256>>>(incT3, attn3, logitsT, nullptr,
                                         384, 1024,
                                         4096LL * 384, 1024LL * 384,
                                         4096LL * 1024, 0);
        colstat_k<<<dim3(16, 4), 1024>>>(logitsT, cmax, csum);
        colwrite_k<<<65536, 256>>>(logitsT, cmax, csum, aT3);
        // out[b, c, pix] = attnT . aT + inc   -> acat half
        wm_gemm<<<dim3(32, 1, 4), 256>>>(attnT3, aT3,
                                         acat + (long long)br * S128, inc,
                                         3072, 4096,
                                         128LL * 3072, 4096LL * 3072,
                                         S256, S128);
    }
    // 14. fused = stdconv 1x1 (256->128) + dif
    gemm128_k<<<dim3(32, 1, 4), 256>>>(fu_w, acat, fuse, fu_b, fu_s, fu_o,
                                       dif, 128, 4096, 256, 0, S256, S128, S128);
    // 15. bilinear x2 upsample
    resize_k<<<32768, 256>>>(fuse, out);
}